// round 12
// baseline (speedup 1.0000x reference)
#include <cuda_runtime.h>
#include <cuda_fp16.h>
#include <math.h>
#include <stdint.h>

#define BB 8
#define NN 20000
#define EE 40000
#define HH 128
#define TT 64
#define LL 4

__device__ __forceinline__ float silu_f(float v) { return v / (1.f + __expf(-v)); }
__device__ __forceinline__ uint32_t s2u(const void* p) {
    uint32_t a;
    asm("{ .reg .u64 t; cvta.to.shared.u64 t, %1; cvt.u32.u64 %0, t; }" : "=r"(a) : "l"(p));
    return a;
}
__device__ __forceinline__ void cp16(uint32_t dst, const void* src) {
    asm volatile("cp.async.cg.shared.global [%0], [%1], 16;\n" :: "r"(dst), "l"(src));
}
#define CP_COMMIT() asm volatile("cp.async.commit_group;\n" ::: "memory")
template <int N> __device__ __forceinline__ void cp_wait() {
    asm volatile("cp.async.wait_group %0;\n" :: "n"(N) : "memory");
}

// ---------------- scratch (static device globals) --------------------------
__device__ float  g_temb[BB * HH];
__device__ float  g_table4[4 * HH];
__device__ float  g_h[BB * NN * HH];
__device__ __half g_htf[BB * NN * HH];
__device__ __half g_agg[BB * NN * HH];
__device__ float  g_x[BB * NN * 3];
__device__ float  g_cupd[BB * NN * 3];
__device__ float  g_dist[BB * EE];
__device__ float  g_cdn[BB * EE * 3];
__device__ __half g_m[BB * EE * HH];
__device__ int    g_deg[NN];
__device__ int    g_off[NN + 1];
__device__ int    g_cur[NN];
__device__ int    g_csr[2 * EE];
__device__ __half g_wm1[4 * 257 * 128];
__device__ __half g_wm2[4 * 128 * 128];
__device__ __half g_wc1[4 * 128 * 128];
__device__ __half g_wn1[4 * 256 * 128];
__device__ __half g_wn2[4 * 128 * 128];
__device__ __half g_wo1[128 * 128];

// ---------------- mma.sync m16n8k16 core (M=128 tile, 4x2 warp grid) -------
#define LDTh 136
#define LDAh 40
#define LDBh 136

__device__ __forceinline__ void mma16(float* c, const uint32_t* a, const uint32_t* b)
{
    asm volatile(
        "mma.sync.aligned.m16n8k16.row.col.f32.f16.f16.f32 "
        "{%0,%1,%2,%3}, {%4,%5,%6,%7}, {%8,%9}, {%0,%1,%2,%3};"
        : "+f"(c[0]), "+f"(c[1]), "+f"(c[2]), "+f"(c[3])
        : "r"(a[0]), "r"(a[1]), "r"(a[2]), "r"(a[3]), "r"(b[0]), "r"(b[1]));
}

__device__ __forceinline__ void mma_chunk32(float (&c)[2][8][4],
        const __half* A, int lda, const __half* Bs, int wm, int wn, int lane)
{
#pragma unroll
    for (int s = 0; s < 2; s++) {
        uint32_t a0[4], a1[4];
        {
            int row = (lane & 7) + ((lane >> 3) & 1) * 8;
            int k   = (lane >> 4) * 8 + s * 16;
            uint32_t ad0 = s2u(A + (wm * 32 + row) * lda + k);
            uint32_t ad1 = s2u(A + (wm * 32 + 16 + row) * lda + k);
            asm volatile("ldmatrix.sync.aligned.m8n8.x4.shared.b16 {%0,%1,%2,%3}, [%4];"
                : "=r"(a0[0]), "=r"(a0[1]), "=r"(a0[2]), "=r"(a0[3]) : "r"(ad0));
            asm volatile("ldmatrix.sync.aligned.m8n8.x4.shared.b16 {%0,%1,%2,%3}, [%4];"
                : "=r"(a1[0]), "=r"(a1[1]), "=r"(a1[2]), "=r"(a1[3]) : "r"(ad1));
        }
#pragma unroll
        for (int jj = 0; jj < 4; jj++) {
            uint32_t bf[4];
            int k = (lane & 15) + s * 16;
            int n = wn * 64 + jj * 16 + (lane >> 4) * 8;
            uint32_t bd = s2u(Bs + k * LDBh + n);
            asm volatile("ldmatrix.sync.aligned.m8n8.x4.trans.shared.b16 {%0,%1,%2,%3}, [%4];"
                : "=r"(bf[0]), "=r"(bf[1]), "=r"(bf[2]), "=r"(bf[3]) : "r"(bd));
            mma16(c[0][2 * jj],     a0, bf);
            mma16(c[0][2 * jj + 1], a0, bf + 2);
            mma16(c[1][2 * jj],     a1, bf);
            mma16(c[1][2 * jj + 1], a1, bf + 2);
        }
    }
}

__device__ __forceinline__ void zero_c(float (&c)[2][8][4])
{
#pragma unroll
    for (int i = 0; i < 2; i++)
#pragma unroll
        for (int j = 0; j < 8; j++)
#pragma unroll
            for (int q = 0; q < 4; q++) c[i][j][q] = 0.f;
}

// 32-row B chunk via cp.async
__device__ __forceinline__ void issue_Bh(const __half* __restrict__ W, int k0,
                                         __half* Bsb, int tid)
{
    int row = tid >> 3;
    int off = (tid & 7) * 16;
    const __half* src = W + (long)(k0 + row) * 128 + off;
    uint32_t dst = s2u(Bsb + row * LDBh + off);
    cp16(dst, src);
    cp16(dst + 16, src + 8);
}

// full 128x128 B matrix via cp.async (8 cp16 / thread)
__device__ __forceinline__ void issue_Bfull(const __half* __restrict__ W,
                                            __half* Bd, int tid)
{
    int row = tid >> 1;
    int off = (tid & 1) * 64;
    const __half* src = W + (long)row * 128 + off;
    uint32_t dst = s2u(Bd + row * LDBh + off);
#pragma unroll
    for (int q = 0; q < 8; q++) cp16(dst + q * 16, src + q * 8);
}

// smem: Th[128*LDTh] | B0[128*LDBh] | B1[128*LDBh]
#define OFF_B0   34816
#define OFF_B1   69632
#define FUSE_SMEM 104448

// ---------------- fused edge kernel ----------------------------------------
__global__ void __launch_bounds__(256, 2)
edge_fused_k(const __half* __restrict__ Wm1h, const float* __restrict__ bm1,
             const float* __restrict__ w256,
             const __half* __restrict__ Wm2h, const float* __restrict__ bm2,
             const __half* __restrict__ Wc1h, const float* __restrict__ bc1,
             const float* __restrict__ Wc2, const int* __restrict__ bonds)
{
    extern __shared__ char dyn[];
    __half* Th = (__half*)dyn;
    __half* B0 = (__half*)(dyn + OFF_B0);
    __half* B1 = (__half*)(dyn + OFF_B1);

    __shared__ float b1s[128], b2s[128], bc1s[128], wc2s[128], wds[128], dists[128];
    __shared__ float cwacc[128];
    __shared__ int nA0[128], nA1[128];

    const int tid = threadIdx.x;
    const int wid = tid >> 5, lane = tid & 31;
    const int wm = wid & 3, wn = wid >> 2;
    const int lr = lane >> 2, lc2 = (lane & 3) * 2;
    const long row0 = (long)blockIdx.x * 128;

    if (tid < 128) {
        b1s[tid] = bm1[tid]; b2s[tid] = bm2[tid];
        bc1s[tid] = bc1[tid]; wc2s[tid] = Wc2[tid]; wds[tid] = w256[tid];
        dists[tid] = g_dist[row0 + tid];
        cwacc[tid] = 0.f;
        long gr = row0 + tid;
        int b = (int)(gr / EE), e = (int)(gr - (long)b * EE);
        nA0[tid] = b * NN + bonds[2 * e];
        nA1[tid] = b * NN + bonds[2 * e + 1];
    }
    __syncthreads();

    const int arow = tid >> 1;
    const int aoff = (tid & 1) * 16;

    auto AB = [&](int i) { return Th + i * 128 * LDAh; };
    auto issue_A = [&](int ch, __half* Asb) {
        int k0 = ch << 5;
        const __half* src = g_htf + (long)((k0 < 128) ? nA0[arow] : nA1[arow]) * HH
                            + (k0 & 127) + aoff;
        uint32_t dst = s2u(Asb + arow * LDAh + aoff);
        cp16(dst, src);
        cp16(dst + 16, src + 8);
    };

    float c[2][8][4];

    // ---- stage 1: m1 = silu(gather @ Wm1 + dist*w256 + b), K=256 ----
    // depth-3 A/B rings, one barrier per chunk; Wm2-full prefetch rides last group
    zero_c(c);
    issue_A(0, AB(0)); issue_Bh(Wm1h, 0, B0, tid); CP_COMMIT();
    issue_A(1, AB(1)); issue_Bh(Wm1h, 32, B0 + 32 * LDBh, tid); CP_COMMIT();
    for (int ch = 0; ch < 8; ch++) {
        if (ch == 7) cp_wait<0>(); else cp_wait<1>();
        __syncthreads();
        if (ch + 2 < 8) {
            int nx = ch + 2;
            issue_A(nx, AB(nx % 3));
            issue_Bh(Wm1h, nx * 32, B0 + (nx % 3) * 32 * LDBh, tid);
            if (ch == 5) issue_Bfull(Wm2h, B1, tid);
            CP_COMMIT();
        }
        mma_chunk32(c, AB(ch % 3), LDAh, B0 + (ch % 3) * 32 * LDBh, wm, wn, lane);
    }
    __syncthreads();
#pragma unroll
    for (int i = 0; i < 2; i++) {
        int r0 = wm * 32 + i * 16 + lr;
        float dv0 = dists[r0], dv1 = dists[r0 + 8];
#pragma unroll
        for (int j = 0; j < 8; j++) {
            int col = wn * 64 + j * 8 + lc2;
            float* cc = c[i][j];
            float v0 = silu_f(cc[0] + b1s[col]     + dv0 * wds[col]);
            float v1 = silu_f(cc[1] + b1s[col + 1] + dv0 * wds[col + 1]);
            float v2 = silu_f(cc[2] + b1s[col]     + dv1 * wds[col]);
            float v3 = silu_f(cc[3] + b1s[col + 1] + dv1 * wds[col + 1]);
            *(__half2*)&Th[r0 * LDTh + col]       = __floats2half2_rn(v0, v1);
            *(__half2*)&Th[(r0 + 8) * LDTh + col] = __floats2half2_rn(v2, v3);
        }
    }
    __syncthreads();

    // ---- stage 2: m = silu(m1 @ Wm2 + b); Wc1 streams into B0 meanwhile ----
    issue_Bfull(Wc1h, B0, tid); CP_COMMIT();
    zero_c(c);
#pragma unroll
    for (int ch = 0; ch < 4; ch++)
        mma_chunk32(c, Th + ch * 32, LDTh, B1 + ch * 32 * LDBh, wm, wn, lane);
    __syncthreads();
#pragma unroll
    for (int i = 0; i < 2; i++) {
        int r0 = wm * 32 + i * 16 + lr;
#pragma unroll
        for (int j = 0; j < 8; j++) {
            int col = wn * 64 + j * 8 + lc2;
            float* cc = c[i][j];
            __half2 h0 = __floats2half2_rn(silu_f(cc[0] + b2s[col]),
                                           silu_f(cc[1] + b2s[col + 1]));
            __half2 h1 = __floats2half2_rn(silu_f(cc[2] + b2s[col]),
                                           silu_f(cc[3] + b2s[col + 1]));
            *(__half2*)&Th[r0 * LDTh + col]       = h0;
            *(__half2*)&Th[(r0 + 8) * LDTh + col] = h1;
            *(__half2*)&g_m[(row0 + r0) * HH + col]     = h0;
            *(__half2*)&g_m[(row0 + r0 + 8) * HH + col] = h1;
        }
    }
    cp_wait<0>();
    __syncthreads();

    // ---- stage 3: cw = silu(m @ Wc1 + b) . Wc2; coord atomics ----
    zero_c(c);
#pragma unroll
    for (int ch = 0; ch < 4; ch++)
        mma_chunk32(c, Th + ch * 32, LDTh, B0 + ch * 32 * LDBh, wm, wn, lane);
#pragma unroll
    for (int i = 0; i < 2; i++) {
        float s0 = 0.f, s1 = 0.f;
#pragma unroll
        for (int j = 0; j < 8; j++) {
            int col = wn * 64 + j * 8 + lc2;
            float* cc = c[i][j];
            s0 += silu_f(cc[0] + bc1s[col]) * wc2s[col]
                + silu_f(cc[1] + bc1s[col + 1]) * wc2s[col + 1];
            s1 += silu_f(cc[2] + bc1s[col]) * wc2s[col]
                + silu_f(cc[3] + bc1s[col + 1]) * wc2s[col + 1];
        }
        s0 += __shfl_xor_sync(0xffffffffu, s0, 1);
        s0 += __shfl_xor_sync(0xffffffffu, s0, 2);
        s1 += __shfl_xor_sync(0xffffffffu, s1, 1);
        s1 += __shfl_xor_sync(0xffffffffu, s1, 2);
        if ((lane & 3) == 0) {
            int r0 = wm * 32 + i * 16 + lr;
            atomicAdd(&cwacc[r0], s0);
            atomicAdd(&cwacc[r0 + 8], s1);
        }
    }
    __syncthreads();
    if (tid < 128) {
        float cw = cwacc[tid];
        long gr = row0 + tid;
        int b = (int)(gr / EE), e = (int)(gr - (long)b * EE);
        int s = bonds[2 * e], d = bonds[2 * e + 1];
        const float* cd = g_cdn + gr * 3;
#pragma unroll
        for (int cc = 0; cc < 3; cc++) {
            float u = cd[cc] * cw;
            atomicAdd(&g_cupd[((long)b * NN + d) * 3 + cc], u);
            atomicAdd(&g_cupd[((long)b * NN + s) * 3 + cc], -u);
        }
    }
}

// ---------------- fused node kernel ----------------------------------------
__global__ void __launch_bounds__(256, 2)
node_fused_k(const __half* __restrict__ Wn1h, const float* __restrict__ bn1,
             const __half* __restrict__ Wn2h, const float* __restrict__ bn2)
{
    extern __shared__ char dyn[];
    __half* Th = (__half*)dyn;
    __half* B0 = (__half*)(dyn + OFF_B0);
    __half* B1 = (__half*)(dyn + OFF_B1);

    __shared__ float b1s[128], b2s[128];

    const int tid = threadIdx.x;
    const int wid = tid >> 5, lane = tid & 31;
    const int wm = wid & 3, wn = wid >> 2;
    const int lr = lane >> 2, lc2 = (lane & 3) * 2;
    const long row0 = (long)blockIdx.x * 128;

    if (tid < 128) { b1s[tid] = bn1[tid]; b2s[tid] = bn2[tid]; }
    __syncthreads();

    const int arow = tid >> 1;
    const int aoff = (tid & 1) * 16;
    const long gra = row0 + arow;

    auto AB = [&](int i) { return Th + i * 128 * LDAh; };
    auto issue_A = [&](int ch, __half* Asb) {
        int k0 = ch << 5;
        const __half* src = ((k0 < 128) ? (g_htf + gra * HH) : (g_agg + gra * HH))
                            + (k0 & 127) + aoff;
        uint32_t dst = s2u(Asb + arow * LDAh + aoff);
        cp16(dst, src);
        cp16(dst + 16, src + 8);
    };

    float c[2][8][4];

    // ---- stage 1: n1 = silu([h|agg] @ Wn1 + b), K=256 ----
    zero_c(c);
    issue_A(0, AB(0)); issue_Bh(Wn1h, 0, B0, tid); CP_COMMIT();
    issue_A(1, AB(1)); issue_Bh(Wn1h, 32, B0 + 32 * LDBh, tid); CP_COMMIT();
    for (int ch = 0; ch < 8; ch++) {
        if (ch == 7) cp_wait<0>(); else cp_wait<1>();
        __syncthreads();
        if (ch + 2 < 8) {
            int nx = ch + 2;
            issue_A(nx, AB(nx % 3));
            issue_Bh(Wn1h, nx * 32, B0 + (nx % 3) * 32 * LDBh, tid);
            if (ch == 5) issue_Bfull(Wn2h, B1, tid);
            CP_COMMIT();
        }
        mma_chunk32(c, AB(ch % 3), LDAh, B0 + (ch % 3) * 32 * LDBh, wm, wn, lane);
    }
    __syncthreads();
#pragma unroll
    for (int i = 0; i < 2; i++) {
        int r0 = wm * 32 + i * 16 + lr;
#pragma unroll
        for (int j = 0; j < 8; j++) {
            int col = wn * 64 + j * 8 + lc2;
            float* cc = c[i][j];
            *(__half2*)&Th[r0 * LDTh + col] =
                __floats2half2_rn(silu_f(cc[0] + b1s[col]), silu_f(cc[1] + b1s[col + 1]));
            *(__half2*)&Th[(r0 + 8) * LDTh + col] =
                __floats2half2_rn(silu_f(cc[2] + b1s[col]), silu_f(cc[3] + b1s[col + 1]));
        }
    }
    __syncthreads();

    // ---- stage 2: h += n1 @ Wn2 + b (refresh g_htf); register epilogue ----
    zero_c(c);
#pragma unroll
    for (int ch = 0; ch < 4; ch++)
        mma_chunk32(c, Th + ch * 32, LDTh, B1 + ch * 32 * LDBh, wm, wn, lane);
#pragma unroll
    for (int i = 0; i < 2; i++) {
        int r0 = wm * 32 + i * 16 + lr;
#pragma unroll
        for (int j = 0; j < 8; j++) {
            int col = wn * 64 + j * 8 + lc2;
            float* cc = c[i][j];
            long base0 = (row0 + r0) * HH + col;
            long base1 = (row0 + r0 + 8) * HH + col;
            float2 h0 = *(float2*)&g_h[base0];
            float2 h1 = *(float2*)&g_h[base1];
            float o0 = h0.x + cc[0] + b2s[col];
            float o1 = h0.y + cc[1] + b2s[col + 1];
            float o2 = h1.x + cc[2] + b2s[col];
            float o3 = h1.y + cc[3] + b2s[col + 1];
            *(float2*)&g_h[base0] = make_float2(o0, o1);
            *(float2*)&g_h[base1] = make_float2(o2, o3);
            *(__half2*)&g_htf[base0] = __floats2half2_rn(o0, o1);
            *(__half2*)&g_htf[base1] = __floats2half2_rn(o2, o3);
        }
    }
}

// ---------------- fused output kernel --------------------------------------
__global__ void __launch_bounds__(256, 2)
out_fused_k(const __half* __restrict__ Wo1h, const float* __restrict__ bo1,
            const float* __restrict__ Wo2, const float* __restrict__ bo2,
            const float* __restrict__ x_in, float* __restrict__ out)
{
    extern __shared__ char dyn[];
    __half* Th = (__half*)dyn;
    __half* B0 = (__half*)(dyn + OFF_B0);

    __shared__ float b1s[128];
    __shared__ float wo2s[128 * 3];
    __shared__ float oacc[128 * 3];

    const int tid = threadIdx.x;
    const int wid = tid >> 5, lane = tid & 31;
    const int wm = wid & 3, wn = wid >> 2;
    const int lr = lane >> 2, lc2 = (lane & 3) * 2;
    const long row0 = (long)blockIdx.x * 128;

    if (tid < 128) b1s[tid] = bo1[tid];
    for (int i = tid; i < 384; i += 256) { wo2s[i] = Wo2[i]; oacc[i] = 0.f; }

    // load full A tile (h) into Th and full Wo1 into B0
    {
        int row = tid >> 1;
        int off = (tid & 1) * 64;
        const __half* src = g_htf + (row0 + row) * HH + off;
        uint32_t dst = s2u(Th + row * LDTh + off);
#pragma unroll
        for (int q = 0; q < 8; q++) cp16(dst + q * 16, src + q * 8);
    }
    issue_Bfull(Wo1h, B0, tid);
    CP_COMMIT();
    cp_wait<0>();
    __syncthreads();

    float c[2][8][4];
    zero_c(c);
#pragma unroll
    for (int ch = 0; ch < 4; ch++)
        mma_chunk32(c, Th + ch * 32, LDTh, B0 + ch * 32 * LDBh, wm, wn, lane);
#pragma unroll
    for (int i = 0; i < 2; i++) {
        float s0[3] = {0.f, 0.f, 0.f};
        float s1[3] = {0.f, 0.f, 0.f};
#pragma unroll
        for (int j = 0; j < 8; j++) {
            int col = wn * 64 + j * 8 + lc2;
            float* cc = c[i][j];
            float v0 = silu_f(cc[0] + b1s[col]);
            float v1 = silu_f(cc[1] + b1s[col + 1]);
            float v2 = silu_f(cc[2] + b1s[col]);
            float v3 = silu_f(cc[3] + b1s[col + 1]);
#pragma unroll
            for (int k = 0; k < 3; k++) {
                s0[k] += v0 * wo2s[col * 3 + k] + v1 * wo2s[(col + 1) * 3 + k];
                s1[k] += v2 * wo2s[col * 3 + k] + v3 * wo2s[(col + 1) * 3 + k];
            }
        }
#pragma unroll
        for (int k = 0; k < 3; k++) {
            s0[k] += __shfl_xor_sync(0xffffffffu, s0[k], 1);
            s0[k] += __shfl_xor_sync(0xffffffffu, s0[k], 2);
            s1[k] += __shfl_xor_sync(0xffffffffu, s1[k], 1);
            s1[k] += __shfl_xor_sync(0xffffffffu, s1[k], 2);
        }
        if ((lane & 3) == 0) {
            int r0 = wm * 32 + i * 16 + lr;
#pragma unroll
            for (int k = 0; k < 3; k++) {
                atomicAdd(&oacc[r0 * 3 + k], s0[k]);
                atomicAdd(&oacc[(r0 + 8) * 3 + k], s1[k]);
            }
        }
    }
    __syncthreads();
    if (tid < 128) {
        long base = (row0 + tid) * 3;
#pragma unroll
        for (int cc = 0; cc < 3; cc++)
            out[base + cc] = oacc[tid * 3 + cc] + bo2[cc] + g_x[base + cc] - x_in[base + cc];
    }
}

// ---------------- setup kernels --------------------------------------------
__global__ void setupA_k(const float* __restrict__ t,
                         const float* __restrict__ W1, const float* __restrict__ b1,
                         const float* __restrict__ W2, const float* __restrict__ b2,
                         const float* __restrict__ emb,
                         const float* __restrict__ Wn, const float* __restrict__ bn,
                         const float* __restrict__ Wm1, const float* __restrict__ Wm2,
                         const float* __restrict__ Wc1, const float* __restrict__ Wn1,
                         const float* __restrict__ Wn2, const float* __restrict__ Wo1)
{
    const int tid = threadIdx.x;
    if (blockIdx.x == 0) {
        __shared__ float te[BB][TT];
        __shared__ float s1[BB][HH];
        const int half = TT / 2;
        for (int idx = tid; idx < BB * TT; idx += 256) {
            int b = idx / TT, k = idx % TT;
            int kk = (k < half) ? k : (k - half);
            float f = __expf((float)kk * (-logf(10000.f) / (float)(half - 1)));
            float a = t[b] * f;
            te[b][k] = (k < half) ? sinf(a) : cosf(a);
        }
        __syncthreads();
        if (tid < 128) {
            for (int b = 0; b < BB; b++) {
                float acc = b1[tid];
                for (int k = 0; k < TT; k++) acc += te[b][k] * W1[k * HH + tid];
                s1[b][tid] = silu_f(acc);
            }
        }
        __syncthreads();
        if (tid < 128) {
            for (int b = 0; b < BB; b++) {
                float acc = b2[tid];
                for (int k = 0; k < HH; k++) acc += s1[b][k] * W2[k * HH + tid];
                g_temb[b * HH + tid] = acc;
            }
        }
    } else if (blockIdx.x == 1) {
        for (int idx = tid; idx < 4 * HH; idx += 256) {
            int a = idx >> 7, j = idx & 127;
            float acc = bn[j];
            for (int k = 0; k < HH; k++) acc += emb[a * HH + k] * Wn[k * HH + j];
            g_table4[idx] = acc;
        }
    } else {
        long rid = (long)(blockIdx.x - 2) * 256 + tid;
        long rstride = (long)(gridDim.x - 2) * 256;
        for (long i = rid; i < 4L * 257 * 128; i += rstride) g_wm1[i] = __float2half_rn(Wm1[i]);
        for (long i = rid; i < 4L * 128 * 128; i += rstride) g_wm2[i] = __float2half_rn(Wm2[i]);
        for (long i = rid; i < 4L * 128 * 128; i += rstride) g_wc1[i] = __float2half_rn(Wc1[i]);
        for (long i = rid; i < 4L * 256 * 128; i += rstride) g_wn1[i] = __float2half_rn(Wn1[i]);
        for (long i = rid; i < 4L * 128 * 128; i += rstride) g_wn2[i] = __float2half_rn(Wn2[i]);
        for (long i = rid; i < 128L * 128; i += rstride)     g_wo1[i] = __float2half_rn(Wo1[i]);
    }
}

__global__ void setupB_k(const int* __restrict__ types, const float* __restrict__ x,
                         const int* __restrict__ bonds)
{
    const long N1 = (long)BB * NN * HH;
    const long N2 = N1 + BB * NN * 3;
    const long N3 = N2 + BB * NN * 3;
    const long N4 = N3 + BB * EE;
    const long stride = (long)gridDim.x * 256;
    for (long idx = (long)blockIdx.x * 256 + threadIdx.x; idx < N4; idx += stride) {
        if (idx < N1) {
            int j = (int)(idx & 127);
            long bn = idx >> 7;
            int n = (int)(bn % NN), b = (int)(bn / NN);
            float v = g_table4[types[n] * HH + j] + g_temb[b * HH + j];
            g_h[idx] = v;
            g_htf[idx] = __float2half_rn(v);
        } else if (idx < N2) {
            long i = idx - N1;
            g_x[i] = x[i];
        } else if (idx < N3) {
            g_cupd[idx - N2] = 0.f;
        } else {
            long i = idx - N3;
            int b = (int)(i / EE), e = (int)(i - (long)b * EE);
            int s = bonds[2 * e], d = bonds[2 * e + 1];
            const float* xs = x + ((long)b * NN + s) * 3;
            const float* xd = x + ((long)b * NN + d) * 3;
            float dx = xd[0] - xs[0], dy = xd[1] - xs[1], dz = xd[2] - xs[2];
            float dist = sqrtf(dx * dx + dy * dy + dz * dz);
            g_dist[i] = dist;
            float inv = 1.f / (dist + 1e-8f);
            g_cdn[i * 3 + 0] = dx * inv;
            g_cdn[i * 3 + 1] = dy * inv;
            g_cdn[i * 3 + 2] = dz * inv;
        }
    }
}

__global__ void prep_k(const int* __restrict__ bonds)
{
    const long N1 = (long)BB * NN * 3;
    const long N2 = N1 + BB * EE;
    const long stride = (long)gridDim.x * 256;
    for (long idx = (long)blockIdx.x * 256 + threadIdx.x; idx < N2; idx += stride) {
        if (idx < N1) {
            g_cupd[idx] = 0.f;
        } else {
            long i = idx - N1;
            int b = (int)(i / EE), e = (int)(i - (long)b * EE);
            int s = bonds[2 * e], d = bonds[2 * e + 1];
            const float* xs = g_x + ((long)b * NN + s) * 3;
            const float* xd = g_x + ((long)b * NN + d) * 3;
            float dx = xd[0] - xs[0], dy = xd[1] - xs[1], dz = xd[2] - xs[2];
            float dist = sqrtf(dx * dx + dy * dy + dz * dz);
            g_dist[i] = dist;
            float inv = 1.f / (dist + 1e-8f);
            g_cdn[i * 3 + 0] = dx * inv;
            g_cdn[i * 3 + 1] = dy * inv;
            g_cdn[i * 3 + 2] = dz * inv;
        }
    }
}

// ---------------- CSR + gather kernels --------------------------------------
__global__ void zero_i_k(int* __restrict__ p, int n)
{
    int idx = blockIdx.x * 256 + threadIdx.x;
    if (idx < n) p[idx] = 0;
}
__global__ void deg_count_k(const int* __restrict__ bonds)
{
    int e = blockIdx.x * 256 + threadIdx.x;
    if (e >= EE) return;
    atomicAdd(&g_deg[bonds[2 * e]], 1);
    atomicAdd(&g_deg[bonds[2 * e + 1]], 1);
}
__global__ void scan_k()
{
    __shared__ int sh[256];
    __shared__ int base;
    int tid = threadIdx.x;
    if (tid == 0) base = 0;
    __syncthreads();
    for (int i0 = 0; i0 < NN; i0 += 256) {
        int i = i0 + tid;
        int v = (i < NN) ? g_deg[i] : 0;
        sh[tid] = v;
        __syncthreads();
        for (int o = 1; o < 256; o <<= 1) {
            int t = (tid >= o) ? sh[tid - o] : 0;
            __syncthreads();
            sh[tid] += t;
            __syncthreads();
        }
        int excl = base + sh[tid] - v;
        if (i < NN) { g_off[i] = excl; g_cur[i] = excl; }
        __syncthreads();
        if (tid == 255) base += sh[255];
        __syncthreads();
    }
    if (tid == 0) g_off[NN] = base;
}
__global__ void fill_k(const int* __restrict__ bonds)
{
    int e = blockIdx.x * 256 + threadIdx.x;
    if (e >= EE) return;
    int s = bonds[2 * e], d = bonds[2 * e + 1];
    int p = atomicAdd(&g_cur[s], 1); g_csr[p] = e;
    int q = atomicAdd(&g_cur[d], 1); g_csr[q] = e;
}

__global__ void agg_gather_k()
{
    int warp = (blockIdx.x * 256 + threadIdx.x) >> 5;
    int lane = threadIdx.x & 31;
    if (warp >= BB * NN) return;
    int b = warp / NN, n = warp - b * NN;
    int o0 = g_off[n], o1 = g_off[n + 1];
    float acc[4] = {0.f, 0.f, 0.f, 0.f};
    for (int j = o0; j < o1; j++) {
        int e = g_csr[j];
        const __half2* row = (const __half2*)(g_m + ((long)b * EE + e) * HH) + lane * 2;
        float2 v0 = __half22float2(row[0]);
        float2 v1 = __half22float2(row[1]);
        acc[0] += v0.x; acc[1] += v0.y; acc[2] += v1.x; acc[3] += v1.y;
    }
    __half2* dst = (__half2*)(g_agg + (long)warp * HH) + lane * 2;
    dst[0] = __floats2half2_rn(acc[0], acc[1]);
    dst[1] = __floats2half2_rn(acc[2], acc[3]);
}

__global__ void x_update_k()
{
    int idx = blockIdx.x * 256 + threadIdx.x;
    if (idx >= BB * NN * 3) return;
    int n = (idx / 3) % NN;
    g_x[idx] += g_cupd[idx] / fmaxf((float)g_deg[n], 1.f);
}

// ---------------- launch ---------------------------------------------------
static inline int cdiv(long n, int b) { return (int)((n + b - 1) / b); }

extern "C" void kernel_launch(void* const* d_in, const int* in_sizes, int n_in,
                              void* d_out, int out_size)
{
    const float* x      = (const float*)d_in[0];
    const float* t      = (const float*)d_in[1];
    const int*   types  = (const int*)d_in[2];
    const int*   bonds  = (const int*)d_in[3];
    const float* emb    = (const float*)d_in[4];
    const float* W_t1   = (const float*)d_in[5];
    const float* b_t1   = (const float*)d_in[6];
    const float* W_t2   = (const float*)d_in[7];
    const float* b_t2   = (const float*)d_in[8];
    const float* W_node = (const float*)d_in[9];
    const float* b_node = (const float*)d_in[10];
    const float* Wm1    = (const float*)d_in[11];
    const float* bm1    = (const float*)d_in[12];
    const float* Wm2    = (const float*)d_in[13];
    const float* bm2    = (const float*)d_in[14];
    const float* Wn1    = (const float*)d_in[15];
    const float* bn1    = (const float*)d_in[16];
    const float* Wn2    = (const float*)d_in[17];
    const float* bn2    = (const float*)d_in[18];
    const float* Wc1    = (const float*)d_in[19];
    const float* bc1    = (const float*)d_in[20];
    const float* Wc2    = (const float*)d_in[21];
    const float* Wo1    = (const float*)d_in[22];
    const float* bo1    = (const float*)d_in[23];
    const float* Wo2    = (const float*)d_in[24];
    const float* bo2    = (const float*)d_in[25];
    float* out = (float*)d_out;

    __half *p_wm1, *p_wm2, *p_wc1, *p_wn1, *p_wn2, *p_wo1;
    int *p_deg;
    cudaGetSymbolAddress((void**)&p_wm1, g_wm1);
    cudaGetSymbolAddress((void**)&p_wm2, g_wm2);
    cudaGetSymbolAddress((void**)&p_wc1, g_wc1);
    cudaGetSymbolAddress((void**)&p_wn1, g_wn1);
    cudaGetSymbolAddress((void**)&p_wn2, g_wn2);
    cudaGetSymbolAddress((void**)&p_wo1, g_wo1);
    cudaGetSymbolAddress((void**)&p_deg, g_deg);

    cudaFuncSetAttribute(edge_fused_k, cudaFuncAttributeMaxDynamicSharedMemorySize, FUSE_SMEM);
    cudaFuncSetAttribute(node_fused_k, cudaFuncAttributeMaxDynamicSharedMemorySize, FUSE_SMEM);
    cudaFuncSetAttribute(out_fused_k, cudaFuncAttributeMaxDynamicSharedMemorySize, FUSE_SMEM);

    const int gridE = BB * EE / 128;  // 2500
    const int gridN = BB * NN / 128;  // 1250

    setupA_k<<<194, 256>>>(t, W_t1, b_t1, W_t2, b_t2, emb, W_node, b_node,
                           Wm1, Wm2, Wc1, Wn1, Wn2, Wo1);
    setupB_k<<<4096, 256>>>(types, x, bonds);
    zero_i_k<<<cdiv(NN, 256), 256>>>(p_deg, NN);

    for (int l = 0; l < LL; l++) {
        if (l > 0) prep_k<<<2048, 256>>>(bonds);

        edge_fused_k<<<gridE, 256, FUSE_SMEM>>>(
            p_wm1 + (long)l * 257 * 128, bm1 + l * 128,
            Wm1 + ((long)l * 257 + 256) * 128,
            p_wm2 + (long)l * 16384, bm2 + l * 128,
            p_wc1 + (long)l * 16384, bc1 + l * 128, Wc2 + l * 128, bonds);

        if (l == 0) {
            deg_count_k<<<cdiv(EE, 256), 256>>>(bonds);
            scan_k<<<1, 256>>>();
            fill_k<<<cdiv(EE, 256), 256>>>(bonds);
        }

        agg_gather_k<<<cdiv((long)BB * NN * 32, 256), 256>>>();

        node_fused_k<<<gridN, 256, FUSE_SMEM>>>(
            p_wn1 + (long)l * 256 * 128, bn1 + l * 128,
            p_wn2 + (long)l * 16384, bn2 + l * 128);

        x_update_k<<<cdiv((long)BB * NN * 3, 256), 256>>>();
    }

    out_fused_k<<<gridN, 256, FUSE_SMEM>>>(p_wo1, bo1, Wo2, bo2, x, out);
}

// round 13
// speedup vs baseline: 1.0458x; 1.0458x over previous
#include <cuda_runtime.h>
#include <cuda_fp16.h>
#include <math.h>
#include <stdint.h>

#define BB 8
#define NN 20000
#define EE 40000
#define HH 128
#define TT 64
#define LL 4

__device__ __forceinline__ float silu_f(float v) { return v / (1.f + __expf(-v)); }
__device__ __forceinline__ uint32_t s2u(const void* p) {
    uint32_t a;
    asm("{ .reg .u64 t; cvta.to.shared.u64 t, %1; cvt.u32.u64 %0, t; }" : "=r"(a) : "l"(p));
    return a;
}
__device__ __forceinline__ void cp16(uint32_t dst, const void* src) {
    asm volatile("cp.async.cg.shared.global [%0], [%1], 16;\n" :: "r"(dst), "l"(src));
}
#define CP_COMMIT() asm volatile("cp.async.commit_group;\n" ::: "memory")
template <int N> __device__ __forceinline__ void cp_wait() {
    asm volatile("cp.async.wait_group %0;\n" :: "n"(N) : "memory");
}

// ---------------- scratch (static device globals) --------------------------
__device__ float  g_temb[BB * HH];
__device__ float  g_table4[4 * HH];
__device__ float  g_h[BB * NN * HH];
__device__ __half g_htf[BB * NN * HH];
__device__ float  g_x[BB * NN * 3];
__device__ float  g_cupd[BB * NN * 3];
__device__ float  g_dist[BB * EE];
__device__ float  g_cdn[BB * EE * 3];
__device__ __half g_m[BB * EE * HH];
__device__ int    g_deg[NN];
__device__ int    g_off[NN + 1];
__device__ int    g_cur[NN];
__device__ int    g_csr[2 * EE];
__device__ __half g_wm1[4 * 257 * 128];
__device__ __half g_wm2[4 * 128 * 128];
__device__ __half g_wc1[4 * 128 * 128];
__device__ __half g_wn1[4 * 256 * 128];
__device__ __half g_wn2[4 * 128 * 128];
__device__ __half g_wo1[128 * 128];

// ---------------- mma.sync m16n8k16 core (M=128 tile, 4x2 warp grid) -------
#define LDTh 136
#define LDAh 40
#define LDBh 136

__device__ __forceinline__ void mma16(float* c, const uint32_t* a, const uint32_t* b)
{
    asm volatile(
        "mma.sync.aligned.m16n8k16.row.col.f32.f16.f16.f32 "
        "{%0,%1,%2,%3}, {%4,%5,%6,%7}, {%8,%9}, {%0,%1,%2,%3};"
        : "+f"(c[0]), "+f"(c[1]), "+f"(c[2]), "+f"(c[3])
        : "r"(a[0]), "r"(a[1]), "r"(a[2]), "r"(a[3]), "r"(b[0]), "r"(b[1]));
}

__device__ __forceinline__ void mma_chunk32(float (&c)[2][8][4],
        const __half* A, int lda, const __half* Bs, int wm, int wn, int lane)
{
#pragma unroll
    for (int s = 0; s < 2; s++) {
        uint32_t a0[4], a1[4];
        {
            int row = (lane & 7) + ((lane >> 3) & 1) * 8;
            int k   = (lane >> 4) * 8 + s * 16;
            uint32_t ad0 = s2u(A + (wm * 32 + row) * lda + k);
            uint32_t ad1 = s2u(A + (wm * 32 + 16 + row) * lda + k);
            asm volatile("ldmatrix.sync.aligned.m8n8.x4.shared.b16 {%0,%1,%2,%3}, [%4];"
                : "=r"(a0[0]), "=r"(a0[1]), "=r"(a0[2]), "=r"(a0[3]) : "r"(ad0));
            asm volatile("ldmatrix.sync.aligned.m8n8.x4.shared.b16 {%0,%1,%2,%3}, [%4];"
                : "=r"(a1[0]), "=r"(a1[1]), "=r"(a1[2]), "=r"(a1[3]) : "r"(ad1));
        }
#pragma unroll
        for (int jj = 0; jj < 4; jj++) {
            uint32_t bf[4];
            int k = (lane & 15) + s * 16;
            int n = wn * 64 + jj * 16 + (lane >> 4) * 8;
            uint32_t bd = s2u(Bs + k * LDBh + n);
            asm volatile("ldmatrix.sync.aligned.m8n8.x4.trans.shared.b16 {%0,%1,%2,%3}, [%4];"
                : "=r"(bf[0]), "=r"(bf[1]), "=r"(bf[2]), "=r"(bf[3]) : "r"(bd));
            mma16(c[0][2 * jj],     a0, bf);
            mma16(c[0][2 * jj + 1], a0, bf + 2);
            mma16(c[1][2 * jj],     a1, bf);
            mma16(c[1][2 * jj + 1], a1, bf + 2);
        }
    }
}

__device__ __forceinline__ void zero_c(float (&c)[2][8][4])
{
#pragma unroll
    for (int i = 0; i < 2; i++)
#pragma unroll
        for (int j = 0; j < 8; j++)
#pragma unroll
            for (int q = 0; q < 4; q++) c[i][j][q] = 0.f;
}

// 32-row B chunk via cp.async
__device__ __forceinline__ void issue_Bh(const __half* __restrict__ W, int k0,
                                         __half* Bsb, int tid)
{
    int row = tid >> 3;
    int off = (tid & 7) * 16;
    const __half* src = W + (long)(k0 + row) * 128 + off;
    uint32_t dst = s2u(Bsb + row * LDBh + off);
    cp16(dst, src);
    cp16(dst + 16, src + 8);
}

// full 128x128 B matrix via cp.async (out kernel only)
__device__ __forceinline__ void issue_Bfull(const __half* __restrict__ W,
                                            __half* Bd, int tid)
{
    int row = tid >> 1;
    int off = (tid & 1) * 64;
    const __half* src = W + (long)row * 128 + off;
    uint32_t dst = s2u(Bd + row * LDBh + off);
#pragma unroll
    for (int q = 0; q < 8; q++) cp16(dst + q * 16, src + q * 8);
}

// smem layouts
#define OFF_BR    34816                         // Th is 34816 B
#define BRCHUNK   (32 * LDBh)                   // halves per B ring buf
#define EDGE_SMEM (34816 + 3 * BRCHUNK * 2)     // 60928
#define OFF_AGG   (34816 + 3 * BRCHUNK * 2)     // 60928
#define NODE_SMEM (OFF_AGG + 128 * LDTh * 2)    // 95744
#define OUT_SMEM  (34816 + 128 * LDBh * 2)      // 69632

// ---------------- fused edge kernel ----------------------------------------
__global__ void __launch_bounds__(256, 2)
edge_fused_k(const __half* __restrict__ Wm1h, const float* __restrict__ bm1,
             const float* __restrict__ w256,
             const __half* __restrict__ Wm2h, const float* __restrict__ bm2,
             const __half* __restrict__ Wc1h, const float* __restrict__ bc1,
             const float* __restrict__ Wc2, const int* __restrict__ bonds)
{
    extern __shared__ char dyn[];
    __half* Th  = (__half*)dyn;
    __half* BRb = (__half*)(dyn + OFF_BR);

    __shared__ float b1s[128], b2s[128], bc1s[128], wc2s[128], wds[128], dists[128];
    __shared__ float cwacc[128];
    __shared__ const __half* pA0[128];
    __shared__ const __half* pA1[128];

    const int tid = threadIdx.x;
    const int wid = tid >> 5, lane = tid & 31;
    const int wm = wid & 3, wn = wid >> 2;
    const int lr = lane >> 2, lc2 = (lane & 3) * 2;
    const long row0 = (long)blockIdx.x * 128;

    if (tid < 128) {
        b1s[tid] = bm1[tid]; b2s[tid] = bm2[tid];
        bc1s[tid] = bc1[tid]; wc2s[tid] = Wc2[tid]; wds[tid] = w256[tid];
        dists[tid] = g_dist[row0 + tid];
        cwacc[tid] = 0.f;
        long gr = row0 + tid;
        int b = (int)(gr / EE), e = (int)(gr - (long)b * EE);
        int s = bonds[2 * e], d = bonds[2 * e + 1];
        pA0[tid] = g_htf + ((long)b * NN + s) * HH;
        pA1[tid] = g_htf + ((long)b * NN + d) * HH;
    }
    __syncthreads();

    const int arow = tid >> 1;
    const int aoff = (tid & 1) * 16;

    auto AB = [&](int i) { return Th + i * 128 * LDAh; };
    auto BR = [&](int i) { return BRb + i * BRCHUNK; };
    auto issue_A = [&](int ch, __half* Asb) {
        int k0 = ch << 5;
        const __half* src = ((k0 < 128) ? pA0[arow] : pA1[arow]) + (k0 & 127) + aoff;
        uint32_t dst = s2u(Asb + arow * LDAh + aoff);
        cp16(dst, src);
        cp16(dst + 16, src + 8);
    };

    float c[2][8][4];

    // ---- stage 1: m1 = silu(gather @ Wm1 + dist*w256 + b), K=256 ----
    zero_c(c);
    issue_A(0, AB(0)); issue_Bh(Wm1h, 0, BR(0), tid); CP_COMMIT();
    issue_A(1, AB(1)); issue_Bh(Wm1h, 32, BR(1), tid); CP_COMMIT();
    for (int ch = 0; ch < 8; ch++) {
        if (ch == 7) cp_wait<0>(); else cp_wait<1>();
        __syncthreads();
        if (ch + 2 < 8) {
            issue_A(ch + 2, AB((ch + 2) % 3));
            issue_Bh(Wm1h, (ch + 2) * 32, BR((ch + 2) % 3), tid);
            CP_COMMIT();
        }
        mma_chunk32(c, AB(ch % 3), LDAh, BR(ch % 3), wm, wn, lane);
    }
    __syncthreads();
#pragma unroll
    for (int i = 0; i < 2; i++) {
        int r0 = wm * 32 + i * 16 + lr;
        float dv0 = dists[r0], dv1 = dists[r0 + 8];
#pragma unroll
        for (int j = 0; j < 8; j++) {
            int col = wn * 64 + j * 8 + lc2;
            float* cc = c[i][j];
            float v0 = silu_f(cc[0] + b1s[col]     + dv0 * wds[col]);
            float v1 = silu_f(cc[1] + b1s[col + 1] + dv0 * wds[col + 1]);
            float v2 = silu_f(cc[2] + b1s[col]     + dv1 * wds[col]);
            float v3 = silu_f(cc[3] + b1s[col + 1] + dv1 * wds[col + 1]);
            *(__half2*)&Th[r0 * LDTh + col]       = __floats2half2_rn(v0, v1);
            *(__half2*)&Th[(r0 + 8) * LDTh + col] = __floats2half2_rn(v2, v3);
        }
    }
    __syncthreads();

    // ---- stage 2: m = silu(m1 @ Wm2 + b) -> g_m and Th ----
    zero_c(c);
    issue_Bh(Wm2h, 0, BR(0), tid); CP_COMMIT();
    issue_Bh(Wm2h, 32, BR(1), tid); CP_COMMIT();
    for (int ch = 0; ch < 4; ch++) {
        if (ch == 3) cp_wait<0>(); else cp_wait<1>();
        __syncthreads();
        if (ch + 2 < 4) { issue_Bh(Wm2h, (ch + 2) * 32, BR((ch + 2) % 3), tid); CP_COMMIT(); }
        mma_chunk32(c, Th + ch * 32, LDTh, BR(ch % 3), wm, wn, lane);
    }
    __syncthreads();
#pragma unroll
    for (int i = 0; i < 2; i++) {
        int r0 = wm * 32 + i * 16 + lr;
#pragma unroll
        for (int j = 0; j < 8; j++) {
            int col = wn * 64 + j * 8 + lc2;
            float* cc = c[i][j];
            __half2 h0 = __floats2half2_rn(silu_f(cc[0] + b2s[col]),
                                           silu_f(cc[1] + b2s[col + 1]));
            __half2 h1 = __floats2half2_rn(silu_f(cc[2] + b2s[col]),
                                           silu_f(cc[3] + b2s[col + 1]));
            *(__half2*)&Th[r0 * LDTh + col]       = h0;
            *(__half2*)&Th[(r0 + 8) * LDTh + col] = h1;
            *(__half2*)&g_m[(row0 + r0) * HH + col]     = h0;
            *(__half2*)&g_m[(row0 + r0 + 8) * HH + col] = h1;
        }
    }
    __syncthreads();

    // ---- stage 3: cw = silu(m @ Wc1 + b) . Wc2; coord atomics ----
    zero_c(c);
    issue_Bh(Wc1h, 0, BR(0), tid); CP_COMMIT();
    issue_Bh(Wc1h, 32, BR(1), tid); CP_COMMIT();
    for (int ch = 0; ch < 4; ch++) {
        if (ch == 3) cp_wait<0>(); else cp_wait<1>();
        __syncthreads();
        if (ch + 2 < 4) { issue_Bh(Wc1h, (ch + 2) * 32, BR((ch + 2) % 3), tid); CP_COMMIT(); }
        mma_chunk32(c, Th + ch * 32, LDTh, BR(ch % 3), wm, wn, lane);
    }
#pragma unroll
    for (int i = 0; i < 2; i++) {
        float s0 = 0.f, s1 = 0.f;
#pragma unroll
        for (int j = 0; j < 8; j++) {
            int col = wn * 64 + j * 8 + lc2;
            float* cc = c[i][j];
            s0 += silu_f(cc[0] + bc1s[col]) * wc2s[col]
                + silu_f(cc[1] + bc1s[col + 1]) * wc2s[col + 1];
            s1 += silu_f(cc[2] + bc1s[col]) * wc2s[col]
                + silu_f(cc[3] + bc1s[col + 1]) * wc2s[col + 1];
        }
        s0 += __shfl_xor_sync(0xffffffffu, s0, 1);
        s0 += __shfl_xor_sync(0xffffffffu, s0, 2);
        s1 += __shfl_xor_sync(0xffffffffu, s1, 1);
        s1 += __shfl_xor_sync(0xffffffffu, s1, 2);
        if ((lane & 3) == 0) {
            int r0 = wm * 32 + i * 16 + lr;
            atomicAdd(&cwacc[r0], s0);
            atomicAdd(&cwacc[r0 + 8], s1);
        }
    }
    __syncthreads();
    if (tid < 128) {
        float cw = cwacc[tid];
        long gr = row0 + tid;
        int b = (int)(gr / EE), e = (int)(gr - (long)b * EE);
        int s = bonds[2 * e], d = bonds[2 * e + 1];
        const float* cd = g_cdn + gr * 3;
#pragma unroll
        for (int cc = 0; cc < 3; cc++) {
            float u = cd[cc] * cw;
            atomicAdd(&g_cupd[((long)b * NN + d) * 3 + cc], u);
            atomicAdd(&g_cupd[((long)b * NN + s) * 3 + cc], -u);
        }
    }
}

// ---------------- fused node kernel (agg computed in-kernel) ----------------
__global__ void __launch_bounds__(256, 2)
node_fused_k(const __half* __restrict__ Wn1h, const float* __restrict__ bn1,
             const __half* __restrict__ Wn2h, const float* __restrict__ bn2)
{
    extern __shared__ char dyn[];
    __half* Th  = (__half*)dyn;
    __half* BRb = (__half*)(dyn + OFF_BR);
    __half* Agg = (__half*)(dyn + OFF_AGG);

    __shared__ float b1s[128], b2s[128];

    const int tid = threadIdx.x;
    const int wid = tid >> 5, lane = tid & 31;
    const int wm = wid & 3, wn = wid >> 2;
    const int lr = lane >> 2, lc2 = (lane & 3) * 2;
    const long row0 = (long)blockIdx.x * 128;

    if (tid < 128) { b1s[tid] = bn1[tid]; b2s[tid] = bn2[tid]; }

    // ---- agg phase: Agg[r][0:128] = sum_{e incident to node(r)} m[b,e,:] ----
    {
#pragma unroll
        for (int pass = 0; pass < 4; pass++) {
            int r = pass * 32 + (tid >> 3);
            int colh = (tid & 7) * 16;
            long gr = row0 + r;
            int b = (int)(gr / NN), n = (int)(gr - (long)b * NN);
            int o0 = g_off[n], o1 = g_off[n + 1];
            float acc[16];
#pragma unroll
            for (int q = 0; q < 16; q++) acc[q] = 0.f;
            for (int j = o0; j < o1; j++) {
                int e = g_csr[j];
                const __half2* src = (const __half2*)(g_m + ((long)b * EE + e) * HH + colh);
#pragma unroll
                for (int q = 0; q < 8; q++) {
                    float2 v = __half22float2(src[q]);
                    acc[2 * q] += v.x; acc[2 * q + 1] += v.y;
                }
            }
            __half2* dst = (__half2*)(Agg + r * LDTh + colh);
#pragma unroll
            for (int q = 0; q < 8; q++) dst[q] = __floats2half2_rn(acc[2 * q], acc[2 * q + 1]);
        }
    }
    __syncthreads();

    const int arow = tid >> 1;
    const int aoff = (tid & 1) * 16;
    const long gra = row0 + arow;

    auto AB = [&](int i) { return Th + i * 128 * LDAh; };
    auto BR = [&](int i) { return BRb + i * BRCHUNK; };
    auto issue_A = [&](int ch, __half* Asb) {   // only chunks 0..3 (h)
        const __half* src = g_htf + gra * HH + (ch << 5) + aoff;
        uint32_t dst = s2u(Asb + arow * LDAh + aoff);
        cp16(dst, src);
        cp16(dst + 16, src + 8);
    };

    float c[2][8][4];

    // ---- stage 1: n1 = silu([h|agg] @ Wn1 + b), K=256; agg chunks from smem ----
    zero_c(c);
    issue_A(0, AB(0)); issue_Bh(Wn1h, 0, BR(0), tid); CP_COMMIT();
    issue_A(1, AB(1)); issue_Bh(Wn1h, 32, BR(1), tid); CP_COMMIT();
    for (int ch = 0; ch < 8; ch++) {
        if (ch == 7) cp_wait<0>(); else cp_wait<1>();
        __syncthreads();
        if (ch + 2 < 8) {
            if (ch + 2 < 4) issue_A(ch + 2, AB((ch + 2) % 3));
            issue_Bh(Wn1h, (ch + 2) * 32, BR((ch + 2) % 3), tid);
            CP_COMMIT();
        }
        if (ch < 4)
            mma_chunk32(c, AB(ch % 3), LDAh, BR(ch % 3), wm, wn, lane);
        else
            mma_chunk32(c, Agg + (ch - 4) * 32, LDTh, BR(ch % 3), wm, wn, lane);
    }
    __syncthreads();
#pragma unroll
    for (int i = 0; i < 2; i++) {
        int r0 = wm * 32 + i * 16 + lr;
#pragma unroll
        for (int j = 0; j < 8; j++) {
            int col = wn * 64 + j * 8 + lc2;
            float* cc = c[i][j];
            *(__half2*)&Th[r0 * LDTh + col] =
                __floats2half2_rn(silu_f(cc[0] + b1s[col]), silu_f(cc[1] + b1s[col + 1]));
            *(__half2*)&Th[(r0 + 8) * LDTh + col] =
                __floats2half2_rn(silu_f(cc[2] + b1s[col]), silu_f(cc[3] + b1s[col + 1]));
        }
    }
    __syncthreads();

    // ---- stage 2: h += n1 @ Wn2 + b (refresh g_htf) ----
    zero_c(c);
    issue_Bh(Wn2h, 0, BR(0), tid); CP_COMMIT();
    issue_Bh(Wn2h, 32, BR(1), tid); CP_COMMIT();
    for (int ch = 0; ch < 4; ch++) {
        if (ch == 3) cp_wait<0>(); else cp_wait<1>();
        __syncthreads();
        if (ch + 2 < 4) { issue_Bh(Wn2h, (ch + 2) * 32, BR((ch + 2) % 3), tid); CP_COMMIT(); }
        mma_chunk32(c, Th + ch * 32, LDTh, BR(ch % 3), wm, wn, lane);
    }
#pragma unroll
    for (int i = 0; i < 2; i++) {
        int r0 = wm * 32 + i * 16 + lr;
#pragma unroll
        for (int j = 0; j < 8; j++) {
            int col = wn * 64 + j * 8 + lc2;
            float* cc = c[i][j];
            long base0 = (row0 + r0) * HH + col;
            long base1 = (row0 + r0 + 8) * HH + col;
            float2 h0 = *(float2*)&g_h[base0];
            float2 h1 = *(float2*)&g_h[base1];
            float o0 = h0.x + cc[0] + b2s[col];
            float o1 = h0.y + cc[1] + b2s[col + 1];
            float o2 = h1.x + cc[2] + b2s[col];
            float o3 = h1.y + cc[3] + b2s[col + 1];
            *(float2*)&g_h[base0] = make_float2(o0, o1);
            *(float2*)&g_h[base1] = make_float2(o2, o3);
            *(__half2*)&g_htf[base0] = __floats2half2_rn(o0, o1);
            *(__half2*)&g_htf[base1] = __floats2half2_rn(o2, o3);
        }
    }
}

// ---------------- fused output kernel --------------------------------------
__global__ void __launch_bounds__(256, 2)
out_fused_k(const __half* __restrict__ Wo1h, const float* __restrict__ bo1,
            const float* __restrict__ Wo2, const float* __restrict__ bo2,
            const float* __restrict__ x_in, float* __restrict__ out)
{
    extern __shared__ char dyn[];
    __half* Th = (__half*)dyn;
    __half* B0 = (__half*)(dyn + OFF_BR);

    __shared__ float b1s[128];
    __shared__ float wo2s[128 * 3];
    __shared__ float oacc[128 * 3];

    const int tid = threadIdx.x;
    const int wid = tid >> 5, lane = tid & 31;
    const int wm = wid & 3, wn = wid >> 2;
    const int lr = lane >> 2, lc2 = (lane & 3) * 2;
    const long row0 = (long)blockIdx.x * 128;

    if (tid < 128) b1s[tid] = bo1[tid];
    for (int i = tid; i < 384; i += 256) { wo2s[i] = Wo2[i]; oacc[i] = 0.f; }

    {
        int row = tid >> 1;
        int off = (tid & 1) * 64;
        const __half* src = g_htf + (row0 + row) * HH + off;
        uint32_t dst = s2u(Th + row * LDTh + off);
#pragma unroll
        for (int q = 0; q < 8; q++) cp16(dst + q * 16, src + q * 8);
    }
    issue_Bfull(Wo1h, B0, tid);
    CP_COMMIT();
    cp_wait<0>();
    __syncthreads();

    float c[2][8][4];
    zero_c(c);
#pragma unroll
    for (int ch = 0; ch < 4; ch++)
        mma_chunk32(c, Th + ch * 32, LDTh, B0 + ch * 32 * LDBh, wm, wn, lane);
#pragma unroll
    for (int i = 0; i < 2; i++) {
        float s0[3] = {0.f, 0.f, 0.f};
        float s1[3] = {0.f, 0.f, 0.f};
#pragma unroll
        for (int j = 0; j < 8; j++) {
            int col = wn * 64 + j * 8 + lc2;
            float* cc = c[i][j];
            float v0 = silu_f(cc[0] + b1s[col]);
            float v1 = silu_f(cc[1] + b1s[col + 1]);
            float v2 = silu_f(cc[2] + b1s[col]);
            float v3 = silu_f(cc[3] + b1s[col + 1]);
#pragma unroll
            for (int k = 0; k < 3; k++) {
                s0[k] += v0 * wo2s[col * 3 + k] + v1 * wo2s[(col + 1) * 3 + k];
                s1[k] += v2 * wo2s[col * 3 + k] + v3 * wo2s[(col + 1) * 3 + k];
            }
        }
#pragma unroll
        for (int k = 0; k < 3; k++) {
            s0[k] += __shfl_xor_sync(0xffffffffu, s0[k], 1);
            s0[k] += __shfl_xor_sync(0xffffffffu, s0[k], 2);
            s1[k] += __shfl_xor_sync(0xffffffffu, s1[k], 1);
            s1[k] += __shfl_xor_sync(0xffffffffu, s1[k], 2);
        }
        if ((lane & 3) == 0) {
            int r0 = wm * 32 + i * 16 + lr;
#pragma unroll
            for (int k = 0; k < 3; k++) {
                atomicAdd(&oacc[r0 * 3 + k], s0[k]);
                atomicAdd(&oacc[(r0 + 8) * 3 + k], s1[k]);
            }
        }
    }
    __syncthreads();
    if (tid < 128) {
        long base = (row0 + tid) * 3;
#pragma unroll
        for (int cc = 0; cc < 3; cc++)
            out[base + cc] = oacc[tid * 3 + cc] + bo2[cc] + g_x[base + cc] - x_in[base + cc];
    }
}

// ---------------- setup kernels --------------------------------------------
__global__ void setupA_k(const float* __restrict__ t,
                         const float* __restrict__ W1, const float* __restrict__ b1,
                         const float* __restrict__ W2, const float* __restrict__ b2,
                         const float* __restrict__ emb,
                         const float* __restrict__ Wn, const float* __restrict__ bn,
                         const float* __restrict__ Wm1, const float* __restrict__ Wm2,
                         const float* __restrict__ Wc1, const float* __restrict__ Wn1,
                         const float* __restrict__ Wn2, const float* __restrict__ Wo1)
{
    const int tid = threadIdx.x;
    if (blockIdx.x == 0) {
        __shared__ float te[BB][TT];
        __shared__ float s1[BB][HH];
        const int half = TT / 2;
        for (int idx = tid; idx < BB * TT; idx += 256) {
            int b = idx / TT, k = idx % TT;
            int kk = (k < half) ? k : (k - half);
            float f = __expf((float)kk * (-logf(10000.f) / (float)(half - 1)));
            float a = t[b] * f;
            te[b][k] = (k < half) ? sinf(a) : cosf(a);
        }
        __syncthreads();
        if (tid < 128) {
            for (int b = 0; b < BB; b++) {
                float acc = b1[tid];
                for (int k = 0; k < TT; k++) acc += te[b][k] * W1[k * HH + tid];
                s1[b][tid] = silu_f(acc);
            }
        }
        __syncthreads();
        if (tid < 128) {
            for (int b = 0; b < BB; b++) {
                float acc = b2[tid];
                for (int k = 0; k < HH; k++) acc += s1[b][k] * W2[k * HH + tid];
                g_temb[b * HH + tid] = acc;
            }
        }
    } else if (blockIdx.x == 1) {
        for (int idx = tid; idx < 4 * HH; idx += 256) {
            int a = idx >> 7, j = idx & 127;
            float acc = bn[j];
            for (int k = 0; k < HH; k++) acc += emb[a * HH + k] * Wn[k * HH + j];
            g_table4[idx] = acc;
        }
    } else {
        long rid = (long)(blockIdx.x - 2) * 256 + tid;
        long rstride = (long)(gridDim.x - 2) * 256;
        for (long i = rid; i < 4L * 257 * 128; i += rstride) g_wm1[i] = __float2half_rn(Wm1[i]);
        for (long i = rid; i < 4L * 128 * 128; i += rstride) g_wm2[i] = __float2half_rn(Wm2[i]);
        for (long i = rid; i < 4L * 128 * 128; i += rstride) g_wc1[i] = __float2half_rn(Wc1[i]);
        for (long i = rid; i < 4L * 256 * 128; i += rstride) g_wn1[i] = __float2half_rn(Wn1[i]);
        for (long i = rid; i < 4L * 128 * 128; i += rstride) g_wn2[i] = __float2half_rn(Wn2[i]);
        for (long i = rid; i < 128L * 128; i += rstride)     g_wo1[i] = __float2half_rn(Wo1[i]);
    }
}

__global__ void setupB_k(const int* __restrict__ types, const float* __restrict__ x,
                         const int* __restrict__ bonds)
{
    const long N1 = (long)BB * NN * HH;
    const long N2 = N1 + BB * NN * 3;
    const long N3 = N2 + BB * NN * 3;
    const long N4 = N3 + BB * EE;
    const long stride = (long)gridDim.x * 256;
    for (long idx = (long)blockIdx.x * 256 + threadIdx.x; idx < N4; idx += stride) {
        if (idx < N1) {
            int j = (int)(idx & 127);
            long bn = idx >> 7;
            int n = (int)(bn % NN), b = (int)(bn / NN);
            float v = g_table4[types[n] * HH + j] + g_temb[b * HH + j];
            g_h[idx] = v;
            g_htf[idx] = __float2half_rn(v);
        } else if (idx < N2) {
            long i = idx - N1;
            g_x[i] = x[i];
        } else if (idx < N3) {
            g_cupd[idx - N2] = 0.f;
        } else {
            long i = idx - N3;
            int b = (int)(i / EE), e = (int)(i - (long)b * EE);
            int s = bonds[2 * e], d = bonds[2 * e + 1];
            const float* xs = x + ((long)b * NN + s) * 3;
            const float* xd = x + ((long)b * NN + d) * 3;
            float dx = xd[0] - xs[0], dy = xd[1] - xs[1], dz = xd[2] - xs[2];
            float dist = sqrtf(dx * dx + dy * dy + dz * dz);
            g_dist[i] = dist;
            float inv = 1.f / (dist + 1e-8f);
            g_cdn[i * 3 + 0] = dx * inv;
            g_cdn[i * 3 + 1] = dy * inv;
            g_cdn[i * 3 + 2] = dz * inv;
        }
    }
}

// per-layer (l>=1): edge geometry from g_x (cupd zero now fused in x_update)
__global__ void prep_k(const int* __restrict__ bonds)
{
    int i = blockIdx.x * 256 + threadIdx.x;
    if (i >= BB * EE) return;
    int b = i / EE, e = i - b * EE;
    int s = bonds[2 * e], d = bonds[2 * e + 1];
    const float* xs = g_x + ((long)b * NN + s) * 3;
    const float* xd = g_x + ((long)b * NN + d) * 3;
    float dx = xd[0] - xs[0], dy = xd[1] - xs[1], dz = xd[2] - xs[2];
    float dist = sqrtf(dx * dx + dy * dy + dz * dz);
    g_dist[i] = dist;
    float inv = 1.f / (dist + 1e-8f);
    g_cdn[i * 3 + 0] = dx * inv;
    g_cdn[i * 3 + 1] = dy * inv;
    g_cdn[i * 3 + 2] = dz * inv;
}

// ---------------- CSR kernels ----------------------------------------------
__global__ void zero_i_k(int* __restrict__ p, int n)
{
    int idx = blockIdx.x * 256 + threadIdx.x;
    if (idx < n) p[idx] = 0;
}
__global__ void deg_count_k(const int* __restrict__ bonds)
{
    int e = blockIdx.x * 256 + threadIdx.x;
    if (e >= EE) return;
    atomicAdd(&g_deg[bonds[2 * e]], 1);
    atomicAdd(&g_deg[bonds[2 * e + 1]], 1);
}
__global__ void scan_k()
{
    __shared__ int sh[256];
    __shared__ int base;
    int tid = threadIdx.x;
    if (tid == 0) base = 0;
    __syncthreads();
    for (int i0 = 0; i0 < NN; i0 += 256) {
        int i = i0 + tid;
        int v = (i < NN) ? g_deg[i] : 0;
        sh[tid] = v;
        __syncthreads();
        for (int o = 1; o < 256; o <<= 1) {
            int t = (tid >= o) ? sh[tid - o] : 0;
            __syncthreads();
            sh[tid] += t;
            __syncthreads();
        }
        int excl = base + sh[tid] - v;
        if (i < NN) { g_off[i] = excl; g_cur[i] = excl; }
        __syncthreads();
        if (tid == 255) base += sh[255];
        __syncthreads();
    }
    if (tid == 0) g_off[NN] = base;
}
__global__ void fill_k(const int* __restrict__ bonds)
{
    int e = blockIdx.x * 256 + threadIdx.x;
    if (e >= EE) return;
    int s = bonds[2 * e], d = bonds[2 * e + 1];
    int p = atomicAdd(&g_cur[s], 1); g_csr[p] = e;
    int q = atomicAdd(&g_cur[d], 1); g_csr[q] = e;
}

__global__ void x_update_k()
{
    int idx = blockIdx.x * 256 + threadIdx.x;
    if (idx >= BB * NN * 3) return;
    int n = (idx / 3) % NN;
    g_x[idx] += g_cupd[idx] / fmaxf((float)g_deg[n], 1.f);
    g_cupd[idx] = 0.f;   // ready for next layer
}

// ---------------- launch ---------------------------------------------------
static inline int cdiv(long n, int b) { return (int)((n + b - 1) / b); }

extern "C" void kernel_launch(void* const* d_in, const int* in_sizes, int n_in,
                              void* d_out, int out_size)
{
    const float* x      = (const float*)d_in[0];
    const float* t      = (const float*)d_in[1];
    const int*   types  = (const int*)d_in[2];
    const int*   bonds  = (const int*)d_in[3];
    const float* emb    = (const float*)d_in[4];
    const float* W_t1   = (const float*)d_in[5];
    const float* b_t1   = (const float*)d_in[6];
    const float* W_t2   = (const float*)d_in[7];
    const float* b_t2   = (const float*)d_in[8];
    const float* W_node = (const float*)d_in[9];
    const float* b_node = (const float*)d_in[10];
    const float* Wm1    = (const float*)d_in[11];
    const float* bm1    = (const float*)d_in[12];
    const float* Wm2    = (const float*)d_in[13];
    const float* bm2    = (const float*)d_in[14];
    const float* Wn1    = (const float*)d_in[15];
    const float* bn1    = (const float*)d_in[16];
    const float* Wn2    = (const float*)d_in[17];
    const float* bn2    = (const float*)d_in[18];
    const float* Wc1    = (const float*)d_in[19];
    const float* bc1    = (const float*)d_in[20];
    const float* Wc2    = (const float*)d_in[21];
    const float* Wo1    = (const float*)d_in[22];
    const float* bo1    = (const float*)d_in[23];
    const float* Wo2    = (const float*)d_in[24];
    const float* bo2    = (const float*)d_in[25];
    float* out = (float*)d_out;

    __half *p_wm1, *p_wm2, *p_wc1, *p_wn1, *p_wn2, *p_wo1;
    int *p_deg;
    cudaGetSymbolAddress((void**)&p_wm1, g_wm1);
    cudaGetSymbolAddress((void**)&p_wm2, g_wm2);
    cudaGetSymbolAddress((void**)&p_wc1, g_wc1);
    cudaGetSymbolAddress((void**)&p_wn1, g_wn1);
    cudaGetSymbolAddress((void**)&p_wn2, g_wn2);
    cudaGetSymbolAddress((void**)&p_wo1, g_wo1);
    cudaGetSymbolAddress((void**)&p_deg, g_deg);

    cudaFuncSetAttribute(edge_fused_k, cudaFuncAttributeMaxDynamicSharedMemorySize, EDGE_SMEM);
    cudaFuncSetAttribute(node_fused_k, cudaFuncAttributeMaxDynamicSharedMemorySize, NODE_SMEM);
    cudaFuncSetAttribute(out_fused_k, cudaFuncAttributeMaxDynamicSharedMemorySize, OUT_SMEM);

    const int gridE = BB * EE / 128;  // 2500
    const int gridN = BB * NN / 128;  // 1250

    setupA_k<<<194, 256>>>(t, W_t1, b_t1, W_t2, b_t2, emb, W_node, b_node,
                           Wm1, Wm2, Wc1, Wn1, Wn2, Wo1);
    setupB_k<<<4096, 256>>>(types, x, bonds);
    zero_i_k<<<cdiv(NN, 256), 256>>>(p_deg, NN);

    for (int l = 0; l < LL; l++) {
        if (l > 0) prep_k<<<cdiv((long)BB * EE, 256), 256>>>(bonds);

        edge_fused_k<<<gridE, 256, EDGE_SMEM>>>(
            p_wm1 + (long)l * 257 * 128, bm1 + l * 128,
            Wm1 + ((long)l * 257 + 256) * 128,
            p_wm2 + (long)l * 16384, bm2 + l * 128,
            p_wc1 + (long)l * 16384, bc1 + l * 128, Wc2 + l * 128, bonds);

        if (l == 0) {
            deg_count_k<<<cdiv(EE, 256), 256>>>(bonds);
            scan_k<<<1, 256>>>();
            fill_k<<<cdiv(EE, 256), 256>>>(bonds);
        }

        node_fused_k<<<gridN, 256, NODE_SMEM>>>(
            p_wn1 + (long)l * 256 * 128, bn1 + l * 128,
            p_wn2 + (long)l * 16384, bn2 + l * 128);

        x_update_k<<<cdiv((long)BB * NN * 3, 256), 256>>>();
    }

    out_fused_k<<<gridN, 256, OUT_SMEM>>>(p_wo1, bo1, Wo2, bo2, x, out);
}

// round 14
// speedup vs baseline: 1.0945x; 1.0465x over previous
#include <cuda_runtime.h>
#include <cuda_fp16.h>
#include <math.h>
#include <stdint.h>

#define BB 8
#define NN 20000
#define EE 40000
#define HH 128
#define TT 64
#define LL 4

__device__ __forceinline__ float silu_f(float v) { return v / (1.f + __expf(-v)); }
__device__ __forceinline__ uint32_t s2u(const void* p) {
    uint32_t a;
    asm("{ .reg .u64 t; cvta.to.shared.u64 t, %1; cvt.u32.u64 %0, t; }" : "=r"(a) : "l"(p));
    return a;
}
__device__ __forceinline__ void cp16(uint32_t dst, const void* src) {
    asm volatile("cp.async.cg.shared.global [%0], [%1], 16;\n" :: "r"(dst), "l"(src));
}
#define CP_COMMIT() asm volatile("cp.async.commit_group;\n" ::: "memory")
template <int N> __device__ __forceinline__ void cp_wait() {
    asm volatile("cp.async.wait_group %0;\n" :: "n"(N) : "memory");
}

// ---------------- scratch (static device globals) --------------------------
__device__ float  g_temb[BB * HH];
__device__ float  g_table4[4 * HH];
__device__ float  g_h[BB * NN * HH];
__device__ __half g_htf[BB * NN * HH];
__device__ __half g_agg[BB * NN * HH];
__device__ float  g_x[BB * NN * 3];
__device__ float  g_cupd[BB * NN * 3];
__device__ float  g_dist[BB * EE];
__device__ float  g_cdn[BB * EE * 3];
__device__ __half g_m[BB * EE * HH];
__device__ int    g_deg[NN];
__device__ int    g_off[NN + 1];
__device__ int    g_cur[NN];
__device__ int    g_csr[2 * EE];
__device__ __half g_wm1[4 * 257 * 128];
__device__ __half g_wm2[4 * 128 * 128];
__device__ __half g_wc1[4 * 128 * 128];
__device__ __half g_wn1[4 * 256 * 128];
__device__ __half g_wn2[4 * 128 * 128];
__device__ __half g_wo1[128 * 128];

// ---------------- mma.sync m16n8k16 core (M=128 tile, 4x2 warp grid) -------
#define LDTh 136
#define LDAh 40
#define LDBh 136

__device__ __forceinline__ void mma16(float* c, const uint32_t* a, const uint32_t* b)
{
    asm volatile(
        "mma.sync.aligned.m16n8k16.row.col.f32.f16.f16.f32 "
        "{%0,%1,%2,%3}, {%4,%5,%6,%7}, {%8,%9}, {%0,%1,%2,%3};"
        : "+f"(c[0]), "+f"(c[1]), "+f"(c[2]), "+f"(c[3])
        : "r"(a[0]), "r"(a[1]), "r"(a[2]), "r"(a[3]), "r"(b[0]), "r"(b[1]));
}

__device__ __forceinline__ void mma_chunk32(float (&c)[2][8][4],
        const __half* A, int lda, const __half* Bs, int wm, int wn, int lane)
{
#pragma unroll
    for (int s = 0; s < 2; s++) {
        uint32_t a0[4], a1[4];
        {
            int row = (lane & 7) + ((lane >> 3) & 1) * 8;
            int k   = (lane >> 4) * 8 + s * 16;
            uint32_t ad0 = s2u(A + (wm * 32 + row) * lda + k);
            uint32_t ad1 = s2u(A + (wm * 32 + 16 + row) * lda + k);
            asm volatile("ldmatrix.sync.aligned.m8n8.x4.shared.b16 {%0,%1,%2,%3}, [%4];"
                : "=r"(a0[0]), "=r"(a0[1]), "=r"(a0[2]), "=r"(a0[3]) : "r"(ad0));
            asm volatile("ldmatrix.sync.aligned.m8n8.x4.shared.b16 {%0,%1,%2,%3}, [%4];"
                : "=r"(a1[0]), "=r"(a1[1]), "=r"(a1[2]), "=r"(a1[3]) : "r"(ad1));
        }
#pragma unroll
        for (int jj = 0; jj < 4; jj++) {
            uint32_t bf[4];
            int k = (lane & 15) + s * 16;
            int n = wn * 64 + jj * 16 + (lane >> 4) * 8;
            uint32_t bd = s2u(Bs + k * LDBh + n);
            asm volatile("ldmatrix.sync.aligned.m8n8.x4.trans.shared.b16 {%0,%1,%2,%3}, [%4];"
                : "=r"(bf[0]), "=r"(bf[1]), "=r"(bf[2]), "=r"(bf[3]) : "r"(bd));
            mma16(c[0][2 * jj],     a0, bf);
            mma16(c[0][2 * jj + 1], a0, bf + 2);
            mma16(c[1][2 * jj],     a1, bf);
            mma16(c[1][2 * jj + 1], a1, bf + 2);
        }
    }
}

__device__ __forceinline__ void zero_c(float (&c)[2][8][4])
{
#pragma unroll
    for (int i = 0; i < 2; i++)
#pragma unroll
        for (int j = 0; j < 8; j++)
#pragma unroll
            for (int q = 0; q < 4; q++) c[i][j][q] = 0.f;
}

// 32-row B chunk via cp.async
__device__ __forceinline__ void issue_Bh(const __half* __restrict__ W, int k0,
                                         __half* Bsb, int tid)
{
    int row = tid >> 3;
    int off = (tid & 7) * 16;
    const __half* src = W + (long)(k0 + row) * 128 + off;
    uint32_t dst = s2u(Bsb + row * LDBh + off);
    cp16(dst, src);
    cp16(dst + 16, src + 8);
}

// full 128x128 B matrix via cp.async (out kernel only)
__device__ __forceinline__ void issue_Bfull(const __half* __restrict__ W,
                                            __half* Bd, int tid)
{
    int row = tid >> 1;
    int off = (tid & 1) * 64;
    const __half* src = W + (long)row * 128 + off;
    uint32_t dst = s2u(Bd + row * LDBh + off);
#pragma unroll
    for (int q = 0; q < 8; q++) cp16(dst + q * 16, src + q * 8);
}

// smem layouts
#define OFF_BR    34816
#define BRCHUNK   (32 * LDBh)
#define FUSE_SMEM (34816 + 3 * BRCHUNK * 2)     // 60928
#define OUT_SMEM  (34816 + 128 * LDBh * 2)      // 69632

// ---------------- fused edge kernel ----------------------------------------
__global__ void __launch_bounds__(256, 2)
edge_fused_k(const __half* __restrict__ Wm1h, const float* __restrict__ bm1,
             const float* __restrict__ w256,
             const __half* __restrict__ Wm2h, const float* __restrict__ bm2,
             const __half* __restrict__ Wc1h, const float* __restrict__ bc1,
             const float* __restrict__ Wc2, const int* __restrict__ bonds)
{
    extern __shared__ char dyn[];
    __half* Th  = (__half*)dyn;
    __half* BRb = (__half*)(dyn + OFF_BR);

    __shared__ float b1s[128], b2s[128], bc1s[128], wc2s[128], wds[128], dists[128];
    __shared__ float cwacc[128];
    __shared__ const __half* pA0[128];
    __shared__ const __half* pA1[128];

    const int tid = threadIdx.x;
    const int wid = tid >> 5, lane = tid & 31;
    const int wm = wid & 3, wn = wid >> 2;
    const int lr = lane >> 2, lc2 = (lane & 3) * 2;
    const long row0 = (long)blockIdx.x * 128;

    if (tid < 128) {
        b1s[tid] = bm1[tid]; b2s[tid] = bm2[tid];
        bc1s[tid] = bc1[tid]; wc2s[tid] = Wc2[tid]; wds[tid] = w256[tid];
        dists[tid] = g_dist[row0 + tid];
        cwacc[tid] = 0.f;
        long gr = row0 + tid;
        int b = (int)(gr / EE), e = (int)(gr - (long)b * EE);
        int s = bonds[2 * e], d = bonds[2 * e + 1];
        pA0[tid] = g_htf + ((long)b * NN + s) * HH;
        pA1[tid] = g_htf + ((long)b * NN + d) * HH;
    }
    __syncthreads();

    const int arow = tid >> 1;
    const int aoff = (tid & 1) * 16;

    auto AB = [&](int i) { return Th + i * 128 * LDAh; };
    auto BR = [&](int i) { return BRb + i * BRCHUNK; };
    auto issue_A = [&](int ch, __half* Asb) {
        int k0 = ch << 5;
        const __half* src = ((k0 < 128) ? pA0[arow] : pA1[arow]) + (k0 & 127) + aoff;
        uint32_t dst = s2u(Asb + arow * LDAh + aoff);
        cp16(dst, src);
        cp16(dst + 16, src + 8);
    };

    float c[2][8][4];

    // ---- stage 1: m1 = silu(gather @ Wm1 + dist*w256 + b), K=256 ----
    zero_c(c);
    issue_A(0, AB(0)); issue_Bh(Wm1h, 0, BR(0), tid); CP_COMMIT();
    issue_A(1, AB(1)); issue_Bh(Wm1h, 32, BR(1), tid); CP_COMMIT();
    for (int ch = 0; ch < 8; ch++) {
        if (ch == 7) cp_wait<0>(); else cp_wait<1>();
        __syncthreads();
        if (ch + 2 < 8) {
            issue_A(ch + 2, AB((ch + 2) % 3));
            issue_Bh(Wm1h, (ch + 2) * 32, BR((ch + 2) % 3), tid);
            CP_COMMIT();
        }
        mma_chunk32(c, AB(ch % 3), LDAh, BR(ch % 3), wm, wn, lane);
    }
    __syncthreads();
#pragma unroll
    for (int i = 0; i < 2; i++) {
        int r0 = wm * 32 + i * 16 + lr;
        float dv0 = dists[r0], dv1 = dists[r0 + 8];
#pragma unroll
        for (int j = 0; j < 8; j++) {
            int col = wn * 64 + j * 8 + lc2;
            float* cc = c[i][j];
            float v0 = silu_f(cc[0] + b1s[col]     + dv0 * wds[col]);
            float v1 = silu_f(cc[1] + b1s[col + 1] + dv0 * wds[col + 1]);
            float v2 = silu_f(cc[2] + b1s[col]     + dv1 * wds[col]);
            float v3 = silu_f(cc[3] + b1s[col + 1] + dv1 * wds[col + 1]);
            *(__half2*)&Th[r0 * LDTh + col]       = __floats2half2_rn(v0, v1);
            *(__half2*)&Th[(r0 + 8) * LDTh + col] = __floats2half2_rn(v2, v3);
        }
    }
    __syncthreads();

    // ---- stage 2: m = silu(m1 @ Wm2 + b) -> g_m and Th ----
    zero_c(c);
    issue_Bh(Wm2h, 0, BR(0), tid); CP_COMMIT();
    issue_Bh(Wm2h, 32, BR(1), tid); CP_COMMIT();
    for (int ch = 0; ch < 4; ch++) {
        if (ch == 3) cp_wait<0>(); else cp_wait<1>();
        __syncthreads();
        if (ch + 2 < 4) { issue_Bh(Wm2h, (ch + 2) * 32, BR((ch + 2) % 3), tid); CP_COMMIT(); }
        mma_chunk32(c, Th + ch * 32, LDTh, BR(ch % 3), wm, wn, lane);
    }
    __syncthreads();
#pragma unroll
    for (int i = 0; i < 2; i++) {
        int r0 = wm * 32 + i * 16 + lr;
#pragma unroll
        for (int j = 0; j < 8; j++) {
            int col = wn * 64 + j * 8 + lc2;
            float* cc = c[i][j];
            __half2 h0 = __floats2half2_rn(silu_f(cc[0] + b2s[col]),
                                           silu_f(cc[1] + b2s[col + 1]));
            __half2 h1 = __floats2half2_rn(silu_f(cc[2] + b2s[col]),
                                           silu_f(cc[3] + b2s[col + 1]));
            *(__half2*)&Th[r0 * LDTh + col]       = h0;
            *(__half2*)&Th[(r0 + 8) * LDTh + col] = h1;
            *(__half2*)&g_m[(row0 + r0) * HH + col]     = h0;
            *(__half2*)&g_m[(row0 + r0 + 8) * HH + col] = h1;
        }
    }
    __syncthreads();

    // ---- stage 3: cw = silu(m @ Wc1 + b) . Wc2; coord atomics ----
    zero_c(c);
    issue_Bh(Wc1h, 0, BR(0), tid); CP_COMMIT();
    issue_Bh(Wc1h, 32, BR(1), tid); CP_COMMIT();
    for (int ch = 0; ch < 4; ch++) {
        if (ch == 3) cp_wait<0>(); else cp_wait<1>();
        __syncthreads();
        if (ch + 2 < 4) { issue_Bh(Wc1h, (ch + 2) * 32, BR((ch + 2) % 3), tid); CP_COMMIT(); }
        mma_chunk32(c, Th + ch * 32, LDTh, BR(ch % 3), wm, wn, lane);
    }
#pragma unroll
    for (int i = 0; i < 2; i++) {
        float s0 = 0.f, s1 = 0.f;
#pragma unroll
        for (int j = 0; j < 8; j++) {
            int col = wn * 64 + j * 8 + lc2;
            float* cc = c[i][j];
            s0 += silu_f(cc[0] + bc1s[col]) * wc2s[col]
                + silu_f(cc[1] + bc1s[col + 1]) * wc2s[col + 1];
            s1 += silu_f(cc[2] + bc1s[col]) * wc2s[col]
                + silu_f(cc[3] + bc1s[col + 1]) * wc2s[col + 1];
        }
        s0 += __shfl_xor_sync(0xffffffffu, s0, 1);
        s0 += __shfl_xor_sync(0xffffffffu, s0, 2);
        s1 += __shfl_xor_sync(0xffffffffu, s1, 1);
        s1 += __shfl_xor_sync(0xffffffffu, s1, 2);
        if ((lane & 3) == 0) {
            int r0 = wm * 32 + i * 16 + lr;
            atomicAdd(&cwacc[r0], s0);
            atomicAdd(&cwacc[r0 + 8], s1);
        }
    }
    __syncthreads();
    if (tid < 128) {
        float cw = cwacc[tid];
        long gr = row0 + tid;
        int b = (int)(gr / EE), e = (int)(gr - (long)b * EE);
        int s = bonds[2 * e], d = bonds[2 * e + 1];
        const float* cd = g_cdn + gr * 3;
#pragma unroll
        for (int cc = 0; cc < 3; cc++) {
            float u = cd[cc] * cw;
            atomicAdd(&g_cupd[((long)b * NN + d) * 3 + cc], u);
            atomicAdd(&g_cupd[((long)b * NN + s) * 3 + cc], -u);
        }
    }
}

// ---------------- fused node kernel (reads g_agg; depth-3 rings) ------------
__global__ void __launch_bounds__(256, 2)
node_fused_k(const __half* __restrict__ Wn1h, const float* __restrict__ bn1,
             const __half* __restrict__ Wn2h, const float* __restrict__ bn2)
{
    extern __shared__ char dyn[];
    __half* Th  = (__half*)dyn;
    __half* BRb = (__half*)(dyn + OFF_BR);

    __shared__ float b1s[128], b2s[128];

    const int tid = threadIdx.x;
    const int wid = tid >> 5, lane = tid & 31;
    const int wm = wid & 3, wn = wid >> 2;
    const int lr = lane >> 2, lc2 = (lane & 3) * 2;
    const long row0 = (long)blockIdx.x * 128;

    if (tid < 128) { b1s[tid] = bn1[tid]; b2s[tid] = bn2[tid]; }
    __syncthreads();

    const int arow = tid >> 1;
    const int aoff = (tid & 1) * 16;
    const long gra = row0 + arow;

    auto AB = [&](int i) { return Th + i * 128 * LDAh; };
    auto BR = [&](int i) { return BRb + i * BRCHUNK; };
    auto issue_A = [&](int ch, __half* Asb) {
        int k0 = ch << 5;
        const __half* src = ((k0 < 128) ? (g_htf + gra * HH) : (g_agg + gra * HH))
                            + (k0 & 127) + aoff;
        uint32_t dst = s2u(Asb + arow * LDAh + aoff);
        cp16(dst, src);
        cp16(dst + 16, src + 8);
    };

    float c[2][8][4];

    // ---- stage 1: n1 = silu([h|agg] @ Wn1 + b), K=256 ----
    zero_c(c);
    issue_A(0, AB(0)); issue_Bh(Wn1h, 0, BR(0), tid); CP_COMMIT();
    issue_A(1, AB(1)); issue_Bh(Wn1h, 32, BR(1), tid); CP_COMMIT();
    for (int ch = 0; ch < 8; ch++) {
        if (ch == 7) cp_wait<0>(); else cp_wait<1>();
        __syncthreads();
        if (ch + 2 < 8) {
            issue_A(ch + 2, AB((ch + 2) % 3));
            issue_Bh(Wn1h, (ch + 2) * 32, BR((ch + 2) % 3), tid);
            CP_COMMIT();
        }
        mma_chunk32(c, AB(ch % 3), LDAh, BR(ch % 3), wm, wn, lane);
    }
    __syncthreads();
#pragma unroll
    for (int i = 0; i < 2; i++) {
        int r0 = wm * 32 + i * 16 + lr;
#pragma unroll
        for (int j = 0; j < 8; j++) {
            int col = wn * 64 + j * 8 + lc2;
            float* cc = c[i][j];
            *(__half2*)&Th[r0 * LDTh + col] =
                __floats2half2_rn(silu_f(cc[0] + b1s[col]), silu_f(cc[1] + b1s[col + 1]));
            *(__half2*)&Th[(r0 + 8) * LDTh + col] =
                __floats2half2_rn(silu_f(cc[2] + b1s[col]), silu_f(cc[3] + b1s[col + 1]));
        }
    }
    __syncthreads();

    // ---- stage 2: h += n1 @ Wn2 + b (refresh g_htf) ----
    zero_c(c);
    issue_Bh(Wn2h, 0, BR(0), tid); CP_COMMIT();
    issue_Bh(Wn2h, 32, BR(1), tid); CP_COMMIT();
    for (int ch = 0; ch < 4; ch++) {
        if (ch == 3) cp_wait<0>(); else cp_wait<1>();
        __syncthreads();
        if (ch + 2 < 4) { issue_Bh(Wn2h, (ch + 2) * 32, BR((ch + 2) % 3), tid); CP_COMMIT(); }
        mma_chunk32(c, Th + ch * 32, LDTh, BR(ch % 3), wm, wn, lane);
    }
#pragma unroll
    for (int i = 0; i < 2; i++) {
        int r0 = wm * 32 + i * 16 + lr;
#pragma unroll
        for (int j = 0; j < 8; j++) {
            int col = wn * 64 + j * 8 + lc2;
            float* cc = c[i][j];
            long base0 = (row0 + r0) * HH + col;
            long base1 = (row0 + r0 + 8) * HH + col;
            float2 h0 = *(float2*)&g_h[base0];
            float2 h1 = *(float2*)&g_h[base1];
            float o0 = h0.x + cc[0] + b2s[col];
            float o1 = h0.y + cc[1] + b2s[col + 1];
            float o2 = h1.x + cc[2] + b2s[col];
            float o3 = h1.y + cc[3] + b2s[col + 1];
            *(float2*)&g_h[base0] = make_float2(o0, o1);
            *(float2*)&g_h[base1] = make_float2(o2, o3);
            *(__half2*)&g_htf[base0] = __floats2half2_rn(o0, o1);
            *(__half2*)&g_htf[base1] = __floats2half2_rn(o2, o3);
        }
    }
}

// ---------------- fused output kernel --------------------------------------
__global__ void __launch_bounds__(256, 2)
out_fused_k(const __half* __restrict__ Wo1h, const float* __restrict__ bo1,
            const float* __restrict__ Wo2, const float* __restrict__ bo2,
            const float* __restrict__ x_in, float* __restrict__ out)
{
    extern __shared__ char dyn[];
    __half* Th = (__half*)dyn;
    __half* B0 = (__half*)(dyn + OFF_BR);

    __shared__ float b1s[128];
    __shared__ float wo2s[128 * 3];
    __shared__ float oacc[128 * 3];

    const int tid = threadIdx.x;
    const int wid = tid >> 5, lane = tid & 31;
    const int wm = wid & 3, wn = wid >> 2;
    const int lr = lane >> 2, lc2 = (lane & 3) * 2;
    const long row0 = (long)blockIdx.x * 128;

    if (tid < 128) b1s[tid] = bo1[tid];
    for (int i = tid; i < 384; i += 256) { wo2s[i] = Wo2[i]; oacc[i] = 0.f; }

    {
        int row = tid >> 1;
        int off = (tid & 1) * 64;
        const __half* src = g_htf + (row0 + row) * HH + off;
        uint32_t dst = s2u(Th + row * LDTh + off);
#pragma unroll
        for (int q = 0; q < 8; q++) cp16(dst + q * 16, src + q * 8);
    }
    issue_Bfull(Wo1h, B0, tid);
    CP_COMMIT();
    cp_wait<0>();
    __syncthreads();

    float c[2][8][4];
    zero_c(c);
#pragma unroll
    for (int ch = 0; ch < 4; ch++)
        mma_chunk32(c, Th + ch * 32, LDTh, B0 + ch * 32 * LDBh, wm, wn, lane);
#pragma unroll
    for (int i = 0; i < 2; i++) {
        float s0[3] = {0.f, 0.f, 0.f};
        float s1[3] = {0.f, 0.f, 0.f};
#pragma unroll
        for (int j = 0; j < 8; j++) {
            int col = wn * 64 + j * 8 + lc2;
            float* cc = c[i][j];
            float v0 = silu_f(cc[0] + b1s[col]);
            float v1 = silu_f(cc[1] + b1s[col + 1]);
            float v2 = silu_f(cc[2] + b1s[col]);
            float v3 = silu_f(cc[3] + b1s[col + 1]);
#pragma unroll
            for (int k = 0; k < 3; k++) {
                s0[k] += v0 * wo2s[col * 3 + k] + v1 * wo2s[(col + 1) * 3 + k];
                s1[k] += v2 * wo2s[col * 3 + k] + v3 * wo2s[(col + 1) * 3 + k];
            }
        }
#pragma unroll
        for (int k = 0; k < 3; k++) {
            s0[k] += __shfl_xor_sync(0xffffffffu, s0[k], 1);
            s0[k] += __shfl_xor_sync(0xffffffffu, s0[k], 2);
            s1[k] += __shfl_xor_sync(0xffffffffu, s1[k], 1);
            s1[k] += __shfl_xor_sync(0xffffffffu, s1[k], 2);
        }
        if ((lane & 3) == 0) {
            int r0 = wm * 32 + i * 16 + lr;
#pragma unroll
            for (int k = 0; k < 3; k++) {
                atomicAdd(&oacc[r0 * 3 + k], s0[k]);
                atomicAdd(&oacc[(r0 + 8) * 3 + k], s1[k]);
            }
        }
    }
    __syncthreads();
    if (tid < 128) {
        long base = (row0 + tid) * 3;
#pragma unroll
        for (int cc = 0; cc < 3; cc++)
            out[base + cc] = oacc[tid * 3 + cc] + bo2[cc] + g_x[base + cc] - x_in[base + cc];
    }
}

// ---------------- setup kernels --------------------------------------------
__global__ void setupA_k(const float* __restrict__ t,
                         const float* __restrict__ W1, const float* __restrict__ b1,
                         const float* __restrict__ W2, const float* __restrict__ b2,
                         const float* __restrict__ emb,
                         const float* __restrict__ Wn, const float* __restrict__ bn,
                         const float* __restrict__ Wm1, const float* __restrict__ Wm2,
                         const float* __restrict__ Wc1, const float* __restrict__ Wn1,
                         const float* __restrict__ Wn2, const float* __restrict__ Wo1)
{
    const int tid = threadIdx.x;
    if (blockIdx.x == 0) {
        __shared__ float te[BB][TT];
        __shared__ float s1[BB][HH];
        const int half = TT / 2;
        for (int idx = tid; idx < BB * TT; idx += 256) {
            int b = idx / TT, k = idx % TT;
            int kk = (k < half) ? k : (k - half);
            float f = __expf((float)kk * (-logf(10000.f) / (float)(half - 1)));
            float a = t[b] * f;
            te[b][k] = (k < half) ? sinf(a) : cosf(a);
        }
        __syncthreads();
        if (tid < 128) {
            for (int b = 0; b < BB; b++) {
                float acc = b1[tid];
                for (int k = 0; k < TT; k++) acc += te[b][k] * W1[k * HH + tid];
                s1[b][tid] = silu_f(acc);
            }
        }
        __syncthreads();
        if (tid < 128) {
            for (int b = 0; b < BB; b++) {
                float acc = b2[tid];
                for (int k = 0; k < HH; k++) acc += s1[b][k] * W2[k * HH + tid];
                g_temb[b * HH + tid] = acc;
            }
        }
    } else if (blockIdx.x == 1) {
        for (int idx = tid; idx < 4 * HH; idx += 256) {
            int a = idx >> 7, j = idx & 127;
            float acc = bn[j];
            for (int k = 0; k < HH; k++) acc += emb[a * HH + k] * Wn[k * HH + j];
            g_table4[idx] = acc;
        }
    } else {
        long rid = (long)(blockIdx.x - 2) * 256 + tid;
        long rstride = (long)(gridDim.x - 2) * 256;
        for (long i = rid; i < 4L * 257 * 128; i += rstride) g_wm1[i] = __float2half_rn(Wm1[i]);
        for (long i = rid; i < 4L * 128 * 128; i += rstride) g_wm2[i] = __float2half_rn(Wm2[i]);
        for (long i = rid; i < 4L * 128 * 128; i += rstride) g_wc1[i] = __float2half_rn(Wc1[i]);
        for (long i = rid; i < 4L * 256 * 128; i += rstride) g_wn1[i] = __float2half_rn(Wn1[i]);
        for (long i = rid; i < 4L * 128 * 128; i += rstride) g_wn2[i] = __float2half_rn(Wn2[i]);
        for (long i = rid; i < 128L * 128; i += rstride)     g_wo1[i] = __float2half_rn(Wo1[i]);
    }
}

__global__ void setupB_k(const int* __restrict__ types, const float* __restrict__ x,
                         const int* __restrict__ bonds)
{
    const long N1 = (long)BB * NN * HH;
    const long N2 = N1 + BB * NN * 3;
    const long N3 = N2 + BB * NN * 3;
    const long N4 = N3 + BB * EE;
    const long stride = (long)gridDim.x * 256;
    for (long idx = (long)blockIdx.x * 256 + threadIdx.x; idx < N4; idx += stride) {
        if (idx < N1) {
            int j = (int)(idx & 127);
            long bn = idx >> 7;
            int n = (int)(bn % NN), b = (int)(bn / NN);
            float v = g_table4[types[n] * HH + j] + g_temb[b * HH + j];
            g_h[idx] = v;
            g_htf[idx] = __float2half_rn(v);
        } else if (idx < N2) {
            long i = idx - N1;
            g_x[i] = x[i];
        } else if (idx < N3) {
            g_cupd[idx - N2] = 0.f;
        } else {
            long i = idx - N3;
            int b = (int)(i / EE), e = (int)(i - (long)b * EE);
            int s = bonds[2 * e], d = bonds[2 * e + 1];
            const float* xs = x + ((long)b * NN + s) * 3;
            const float* xd = x + ((long)b * NN + d) * 3;
            float dx = xd[0] - xs[0], dy = xd[1] - xs[1], dz = xd[2] - xs[2];
            float dist = sqrtf(dx * dx + dy * dy + dz * dz);
            g_dist[i] = dist;
            float inv = 1.f / (dist + 1e-8f);
            g_cdn[i * 3 + 0] = dx * inv;
            g_cdn[i * 3 + 1] = dy * inv;
            g_cdn[i * 3 + 2] = dz * inv;
        }
    }
}

// per-layer (l>=1): edge geometry from g_x
__global__ void prep_k(const int* __restrict__ bonds)
{
    int i = blockIdx.x * 256 + threadIdx.x;
    if (i >= BB * EE) return;
    int b = i / EE, e = i - b * EE;
    int s = bonds[2 * e], d = bonds[2 * e + 1];
    const float* xs = g_x + ((long)b * NN + s) * 3;
    const float* xd = g_x + ((long)b * NN + d) * 3;
    float dx = xd[0] - xs[0], dy = xd[1] - xs[1], dz = xd[2] - xs[2];
    float dist = sqrtf(dx * dx + dy * dy + dz * dz);
    g_dist[i] = dist;
    float inv = 1.f / (dist + 1e-8f);
    g_cdn[i * 3 + 0] = dx * inv;
    g_cdn[i * 3 + 1] = dy * inv;
    g_cdn[i * 3 + 2] = dz * inv;
}

// ---------------- CSR + gather kernels --------------------------------------
__global__ void zero_i_k(int* __restrict__ p, int n)
{
    int idx = blockIdx.x * 256 + threadIdx.x;
    if (idx < n) p[idx] = 0;
}
__global__ void deg_count_k(const int* __restrict__ bonds)
{
    int e = blockIdx.x * 256 + threadIdx.x;
    if (e >= EE) return;
    atomicAdd(&g_deg[bonds[2 * e]], 1);
    atomicAdd(&g_deg[bonds[2 * e + 1]], 1);
}
__global__ void scan_k()
{
    __shared__ int sh[256];
    __shared__ int base;
    int tid = threadIdx.x;
    if (tid == 0) base = 0;
    __syncthreads();
    for (int i0 = 0; i0 < NN; i0 += 256) {
        int i = i0 + tid;
        int v = (i < NN) ? g_deg[i] : 0;
        sh[tid] = v;
        __syncthreads();
        for (int o = 1; o < 256; o <<= 1) {
            int t = (tid >= o) ? sh[tid - o] : 0;
            __syncthreads();
            sh[tid] += t;
            __syncthreads();
        }
        int excl = base + sh[tid] - v;
        if (i < NN) { g_off[i] = excl; g_cur[i] = excl; }
        __syncthreads();
        if (tid == 255) base += sh[255];
        __syncthreads();
    }
    if (tid == 0) g_off[NN] = base;
}
__global__ void fill_k(const int* __restrict__ bonds)
{
    int e = blockIdx.x * 256 + threadIdx.x;
    if (e >= EE) return;
    int s = bonds[2 * e], d = bonds[2 * e + 1];
    int p = atomicAdd(&g_cur[s], 1); g_csr[p] = e;
    int q = atomicAdd(&g_cur[d], 1); g_csr[q] = e;
}

__global__ void agg_gather_k()
{
    int warp = (blockIdx.x * 256 + threadIdx.x) >> 5;
    int lane = threadIdx.x & 31;
    if (warp >= BB * NN) return;
    int b = warp / NN, n = warp - b * NN;
    int o0 = g_off[n], o1 = g_off[n + 1];
    float acc[4] = {0.f, 0.f, 0.f, 0.f};
    for (int j = o0; j < o1; j++) {
        int e = g_csr[j];
        const __half2* row = (const __half2*)(g_m + ((long)b * EE + e) * HH) + lane * 2;
        float2 v0 = __half22float2(row[0]);
        float2 v1 = __half22float2(row[1]);
        acc[0] += v0.x; acc[1] += v0.y; acc[2] += v1.x; acc[3] += v1.y;
    }
    __half2* dst = (__half2*)(g_agg + (long)warp * HH) + lane * 2;
    dst[0] = __floats2half2_rn(acc[0], acc[1]);
    dst[1] = __floats2half2_rn(acc[2], acc[3]);
}

__global__ void x_update_k()
{
    int idx = blockIdx.x * 256 + threadIdx.x;
    if (idx >= BB * NN * 3) return;
    int n = (idx / 3) % NN;
    g_x[idx] += g_cupd[idx] / fmaxf((float)g_deg[n], 1.f);
    g_cupd[idx] = 0.f;
}

// ---------------- launch ---------------------------------------------------
static inline int cdiv(long n, int b) { return (int)((n + b - 1) / b); }

extern "C" void kernel_launch(void* const* d_in, const int* in_sizes, int n_in,
                              void* d_out, int out_size)
{
    const float* x      = (const float*)d_in[0];
    const float* t      = (const float*)d_in[1];
    const int*   types  = (const int*)d_in[2];
    const int*   bonds  = (const int*)d_in[3];
    const float* emb    = (const float*)d_in[4];
    const float* W_t1   = (const float*)d_in[5];
    const float* b_t1   = (const float*)d_in[6];
    const float* W_t2   = (const float*)d_in[7];
    const float* b_t2   = (const float*)d_in[8];
    const float* W_node = (const float*)d_in[9];
    const float* b_node = (const float*)d_in[10];
    const float* Wm1    = (const float*)d_in[11];
    const float* bm1    = (const float*)d_in[12];
    const float* Wm2    = (const float*)d_in[13];
    const float* bm2    = (const float*)d_in[14];
    const float* Wn1    = (const float*)d_in[15];
    const float* bn1    = (const float*)d_in[16];
    const float* Wn2    = (const float*)d_in[17];
    const float* bn2    = (const float*)d_in[18];
    const float* Wc1    = (const float*)d_in[19];
    const float* bc1    = (const float*)d_in[20];
    const float* Wc2    = (const float*)d_in[21];
    const float* Wo1    = (const float*)d_in[22];
    const float* bo1    = (const float*)d_in[23];
    const float* Wo2    = (const float*)d_in[24];
    const float* bo2    = (const float*)d_in[25];
    float* out = (float*)d_out;

    __half *p_wm1, *p_wm2, *p_wc1, *p_wn1, *p_wn2, *p_wo1;
    int *p_deg;
    cudaGetSymbolAddress((void**)&p_wm1, g_wm1);
    cudaGetSymbolAddress((void**)&p_wm2, g_wm2);
    cudaGetSymbolAddress((void**)&p_wc1, g_wc1);
    cudaGetSymbolAddress((void**)&p_wn1, g_wn1);
    cudaGetSymbolAddress((void**)&p_wn2, g_wn2);
    cudaGetSymbolAddress((void**)&p_wo1, g_wo1);
    cudaGetSymbolAddress((void**)&p_deg, g_deg);

    cudaFuncSetAttribute(edge_fused_k, cudaFuncAttributeMaxDynamicSharedMemorySize, FUSE_SMEM);
    cudaFuncSetAttribute(node_fused_k, cudaFuncAttributeMaxDynamicSharedMemorySize, FUSE_SMEM);
    cudaFuncSetAttribute(out_fused_k, cudaFuncAttributeMaxDynamicSharedMemorySize, OUT_SMEM);

    const int gridE = BB * EE / 128;  // 2500
    const int gridN = BB * NN / 128;  // 1250

    setupA_k<<<194, 256>>>(t, W_t1, b_t1, W_t2, b_t2, emb, W_node, b_node,
                           Wm1, Wm2, Wc1, Wn1, Wn2, Wo1);
    setupB_k<<<4096, 256>>>(types, x, bonds);
    zero_i_k<<<cdiv(NN, 256), 256>>>(p_deg, NN);

    for (int l = 0; l < LL; l++) {
        if (l > 0) prep_k<<<cdiv((long)BB * EE, 256), 256>>>(bonds);

        edge_fused_k<<<gridE, 256, FUSE_SMEM>>>(
            p_wm1 + (long)l * 257 * 128, bm1 + l * 128,
            Wm1 + ((long)l * 257 + 256) * 128,
            p_wm2 + (long)l * 16384, bm2 + l * 128,
            p_wc1 + (long)l * 16384, bc1 + l * 128, Wc2 + l * 128, bonds);

        if (l == 0) {
            deg_count_k<<<cdiv(EE, 256), 256>>>(bonds);
            scan_k<<<1, 256>>>();
            fill_k<<<cdiv(EE, 256), 256>>>(bonds);
        }

        agg_gather_k<<<cdiv((long)BB * NN * 32, 256), 256>>>();

        node_fused_k<<<gridN, 256, FUSE_SMEM>>>(
            p_wn1 + (long)l * 256 * 128, bn1 + l * 128,
            p_wn2 + (long)l * 16384, bn2 + l * 128);

        x_update_k<<<cdiv((long)BB * NN * 3, 256), 256>>>();
    }

    out_fused_k<<<gridN, 256, OUT_SMEM>>>(p_wo1, bo1, Wo2, bo2, x, out);
}

// round 15
// speedup vs baseline: 1.3065x; 1.1937x over previous
#include <cuda_runtime.h>
#include <cuda_fp16.h>
#include <math.h>
#include <stdint.h>

#define BB 8
#define NN 20000
#define EE 40000
#define HH 128
#define TT 64
#define LL 4

__device__ __forceinline__ float silu_f(float v) {
    return __fdividef(v, 1.f + __expf(-v));
}
__device__ __forceinline__ uint32_t s2u(const void* p) {
    uint32_t a;
    asm("{ .reg .u64 t; cvta.to.shared.u64 t, %1; cvt.u32.u64 %0, t; }" : "=r"(a) : "l"(p));
    return a;
}
__device__ __forceinline__ void cp16(uint32_t dst, const void* src) {
    asm volatile("cp.async.cg.shared.global [%0], [%1], 16;\n" :: "r"(dst), "l"(src));
}
#define CP_COMMIT() asm volatile("cp.async.commit_group;\n" ::: "memory")
template <int N> __device__ __forceinline__ void cp_wait() {
    asm volatile("cp.async.wait_group %0;\n" :: "n"(N) : "memory");
}

// ---------------- scratch (static device globals) --------------------------
__device__ float  g_temb[BB * HH];
__device__ float  g_table4[4 * HH];
__device__ float  g_h[BB * NN * HH];
__device__ __half g_htf[BB * NN * HH];
__device__ __half g_agg[BB * NN * HH];
__device__ float  g_x[BB * NN * 3];
__device__ float  g_cupd[BB * NN * 3];
__device__ float  g_dist[BB * EE];
__device__ float  g_cdn[BB * EE * 3];
__device__ __half g_m[BB * EE * HH];
__device__ int    g_deg[NN];
__device__ int    g_off[NN + 1];
__device__ int    g_cur[NN];
__device__ int    g_csr[2 * EE];
__device__ __half g_wm1[4 * 257 * 128];
__device__ __half g_wm2[4 * 128 * 128];
__device__ __half g_wc1[4 * 128 * 128];
__device__ __half g_wn1[4 * 256 * 128];
__device__ __half g_wn2[4 * 128 * 128];
__device__ __half g_wo1[128 * 128];

// ---------------- mma.sync m16n8k16 core (M=128 tile, 4x2 warp grid) -------
#define LDTh 136
#define LDAh 40
#define LDBh 136

__device__ __forceinline__ void mma16(float* c, const uint32_t* a, const uint32_t* b)
{
    asm volatile(
        "mma.sync.aligned.m16n8k16.row.col.f32.f16.f16.f32 "
        "{%0,%1,%2,%3}, {%4,%5,%6,%7}, {%8,%9}, {%0,%1,%2,%3};"
        : "+f"(c[0]), "+f"(c[1]), "+f"(c[2]), "+f"(c[3])
        : "r"(a[0]), "r"(a[1]), "r"(a[2]), "r"(a[3]), "r"(b[0]), "r"(b[1]));
}

__device__ __forceinline__ void mma_chunk32(float (&c)[2][8][4],
        const __half* A, int lda, const __half* Bs, int wm, int wn, int lane)
{
#pragma unroll
    for (int s = 0; s < 2; s++) {
        uint32_t a0[4], a1[4];
        {
            int row = (lane & 7) + ((lane >> 3) & 1) * 8;
            int k   = (lane >> 4) * 8 + s * 16;
            uint32_t ad0 = s2u(A + (wm * 32 + row) * lda + k);
            uint32_t ad1 = s2u(A + (wm * 32 + 16 + row) * lda + k);
            asm volatile("ldmatrix.sync.aligned.m8n8.x4.shared.b16 {%0,%1,%2,%3}, [%4];"
                : "=r"(a0[0]), "=r"(a0[1]), "=r"(a0[2]), "=r"(a0[3]) : "r"(ad0));
            asm volatile("ldmatrix.sync.aligned.m8n8.x4.shared.b16 {%0,%1,%2,%3}, [%4];"
                : "=r"(a1[0]), "=r"(a1[1]), "=r"(a1[2]), "=r"(a1[3]) : "r"(ad1));
        }
#pragma unroll
        for (int jj = 0; jj < 4; jj++) {
            uint32_t bf[4];
            int k = (lane & 15) + s * 16;
            int n = wn * 64 + jj * 16 + (lane >> 4) * 8;
            uint32_t bd = s2u(Bs + k * LDBh + n);
            asm volatile("ldmatrix.sync.aligned.m8n8.x4.trans.shared.b16 {%0,%1,%2,%3}, [%4];"
                : "=r"(bf[0]), "=r"(bf[1]), "=r"(bf[2]), "=r"(bf[3]) : "r"(bd));
            mma16(c[0][2 * jj],     a0, bf);
            mma16(c[0][2 * jj + 1], a0, bf + 2);
            mma16(c[1][2 * jj],     a1, bf);
            mma16(c[1][2 * jj + 1], a1, bf + 2);
        }
    }
}

__device__ __forceinline__ void zero_c(float (&c)[2][8][4])
{
#pragma unroll
    for (int i = 0; i < 2; i++)
#pragma unroll
        for (int j = 0; j < 8; j++)
#pragma unroll
            for (int q = 0; q < 4; q++) c[i][j][q] = 0.f;
}

// 32-row B chunk via cp.async
__device__ __forceinline__ void issue_Bh(const __half* __restrict__ W, int k0,
                                         __half* Bsb, int tid)
{
    int row = tid >> 3;
    int off = (tid & 7) * 16;
    const __half* src = W + (long)(k0 + row) * 128 + off;
    uint32_t dst = s2u(Bsb + row * LDBh + off);
    cp16(dst, src);
    cp16(dst + 16, src + 8);
}

// full 128x128 B matrix via cp.async (out kernel only)
__device__ __forceinline__ void issue_Bfull(const __half* __restrict__ W,
                                            __half* Bd, int tid)
{
    int row = tid >> 1;
    int off = (tid & 1) * 64;
    const __half* src = W + (long)row * 128 + off;
    uint32_t dst = s2u(Bd + row * LDBh + off);
#pragma unroll
    for (int q = 0; q < 8; q++) cp16(dst + q * 16, src + q * 8);
}

// smem layouts
#define OFF_BR    34816
#define BRCHUNK   (32 * LDBh)
#define FUSE_SMEM (34816 + 3 * BRCHUNK * 2)     // 60928
#define OUT_SMEM  (34816 + 128 * LDBh * 2)      // 69632

// ---------------- fused edge kernel ----------------------------------------
__global__ void __launch_bounds__(256, 2)
edge_fused_k(const __half* __restrict__ Wm1h, const float* __restrict__ bm1,
             const float* __restrict__ w256,
             const __half* __restrict__ Wm2h, const float* __restrict__ bm2,
             const __half* __restrict__ Wc1h, const float* __restrict__ bc1,
             const float* __restrict__ Wc2, const int* __restrict__ bonds)
{
    extern __shared__ char dyn[];
    __half* Th  = (__half*)dyn;
    __half* BRb = (__half*)(dyn + OFF_BR);

    __shared__ float b1s[128], b2s[128], bc1s[128], wc2s[128], wds[128], dists[128];
    __shared__ float cwacc[128];
    __shared__ const __half* pA0[128];
    __shared__ const __half* pA1[128];

    const int tid = threadIdx.x;
    const int wid = tid >> 5, lane = tid & 31;
    const int wm = wid & 3, wn = wid >> 2;
    const int lr = lane >> 2, lc2 = (lane & 3) * 2;
    const long row0 = (long)blockIdx.x * 128;

    if (tid < 128) {
        b1s[tid] = bm1[tid]; b2s[tid] = bm2[tid];
        bc1s[tid] = bc1[tid]; wc2s[tid] = Wc2[tid]; wds[tid] = w256[tid];
        dists[tid] = g_dist[row0 + tid];
        cwacc[tid] = 0.f;
        long gr = row0 + tid;
        int b = (int)(gr / EE), e = (int)(gr - (long)b * EE);
        int s = bonds[2 * e], d = bonds[2 * e + 1];
        pA0[tid] = g_htf + ((long)b * NN + s) * HH;
        pA1[tid] = g_htf + ((long)b * NN + d) * HH;
    }
    __syncthreads();

    const int arow = tid >> 1;
    const int aoff = (tid & 1) * 16;

    auto AB = [&](int i) { return Th + i * 128 * LDAh; };
    auto BR = [&](int i) { return BRb + i * BRCHUNK; };
    auto issue_A = [&](int ch, __half* Asb) {
        int k0 = ch << 5;
        const __half* src = ((k0 < 128) ? pA0[arow] : pA1[arow]) + (k0 & 127) + aoff;
        uint32_t dst = s2u(Asb + arow * LDAh + aoff);
        cp16(dst, src);
        cp16(dst + 16, src + 8);
    };

    float c[2][8][4];

    // ---- stage 1: m1 = silu(gather @ Wm1 + dist*w256 + b), K=256 ----
    zero_c(c);
    issue_A(0, AB(0)); issue_Bh(Wm1h, 0, BR(0), tid); CP_COMMIT();
    issue_A(1, AB(1)); issue_Bh(Wm1h, 32, BR(1), tid); CP_COMMIT();
    for (int ch = 0; ch < 8; ch++) {
        if (ch == 7) cp_wait<0>(); else cp_wait<1>();
        __syncthreads();
        if (ch + 2 < 8) {
            issue_A(ch + 2, AB((ch + 2) % 3));
            issue_Bh(Wm1h, (ch + 2) * 32, BR((ch + 2) % 3), tid);
            CP_COMMIT();
        }
        mma_chunk32(c, AB(ch % 3), LDAh, BR(ch % 3), wm, wn, lane);
    }
    __syncthreads();
    // prefetch stage-2 B chunks 0,1 so the epilogue hides their latency
    issue_Bh(Wm2h, 0, BR(0), tid); CP_COMMIT();
    issue_Bh(Wm2h, 32, BR(1), tid); CP_COMMIT();
#pragma unroll
    for (int i = 0; i < 2; i++) {
        int r0 = wm * 32 + i * 16 + lr;
        float dv0 = dists[r0], dv1 = dists[r0 + 8];
#pragma unroll
        for (int j = 0; j < 8; j++) {
            int col = wn * 64 + j * 8 + lc2;
            float* cc = c[i][j];
            float v0 = silu_f(cc[0] + b1s[col]     + dv0 * wds[col]);
            float v1 = silu_f(cc[1] + b1s[col + 1] + dv0 * wds[col + 1]);
            float v2 = silu_f(cc[2] + b1s[col]     + dv1 * wds[col]);
            float v3 = silu_f(cc[3] + b1s[col + 1] + dv1 * wds[col + 1]);
            *(__half2*)&Th[r0 * LDTh + col]       = __floats2half2_rn(v0, v1);
            *(__half2*)&Th[(r0 + 8) * LDTh + col] = __floats2half2_rn(v2, v3);
        }
    }
    __syncthreads();

    // ---- stage 2: m = silu(m1 @ Wm2 + b) -> g_m and Th ----
    zero_c(c);
    for (int ch = 0; ch < 4; ch++) {
        if (ch == 3) cp_wait<0>(); else cp_wait<1>();
        __syncthreads();
        if (ch + 2 < 4) { issue_Bh(Wm2h, (ch + 2) * 32, BR((ch + 2) % 3), tid); CP_COMMIT(); }
        mma_chunk32(c, Th + ch * 32, LDTh, BR(ch % 3), wm, wn, lane);
    }
    __syncthreads();
    // prefetch stage-3 B chunks 0,1 behind the epilogue
    issue_Bh(Wc1h, 0, BR(0), tid); CP_COMMIT();
    issue_Bh(Wc1h, 32, BR(1), tid); CP_COMMIT();
#pragma unroll
    for (int i = 0; i < 2; i++) {
        int r0 = wm * 32 + i * 16 + lr;
#pragma unroll
        for (int j = 0; j < 8; j++) {
            int col = wn * 64 + j * 8 + lc2;
            float* cc = c[i][j];
            __half2 h0 = __floats2half2_rn(silu_f(cc[0] + b2s[col]),
                                           silu_f(cc[1] + b2s[col + 1]));
            __half2 h1 = __floats2half2_rn(silu_f(cc[2] + b2s[col]),
                                           silu_f(cc[3] + b2s[col + 1]));
            *(__half2*)&Th[r0 * LDTh + col]       = h0;
            *(__half2*)&Th[(r0 + 8) * LDTh + col] = h1;
            *(__half2*)&g_m[(row0 + r0) * HH + col]     = h0;
            *(__half2*)&g_m[(row0 + r0 + 8) * HH + col] = h1;
        }
    }
    __syncthreads();

    // ---- stage 3: cw = silu(m @ Wc1 + b) . Wc2; coord atomics ----
    zero_c(c);
    for (int ch = 0; ch < 4; ch++) {
        if (ch == 3) cp_wait<0>(); else cp_wait<1>();
        __syncthreads();
        if (ch + 2 < 4) { issue_Bh(Wc1h, (ch + 2) * 32, BR((ch + 2) % 3), tid); CP_COMMIT(); }
        mma_chunk32(c, Th + ch * 32, LDTh, BR(ch % 3), wm, wn, lane);
    }
#pragma unroll
    for (int i = 0; i < 2; i++) {
        float s0 = 0.f, s1 = 0.f;
#pragma unroll
        for (int j = 0; j < 8; j++) {
            int col = wn * 64 + j * 8 + lc2;
            float* cc = c[i][j];
            s0 += silu_f(cc[0] + bc1s[col]) * wc2s[col]
                + silu_f(cc[1] + bc1s[col + 1]) * wc2s[col + 1];
            s1 += silu_f(cc[2] + bc1s[col]) * wc2s[col]
                + silu_f(cc[3] + bc1s[col + 1]) * wc2s[col + 1];
        }
        s0 += __shfl_xor_sync(0xffffffffu, s0, 1);
        s0 += __shfl_xor_sync(0xffffffffu, s0, 2);
        s1 += __shfl_xor_sync(0xffffffffu, s1, 1);
        s1 += __shfl_xor_sync(0xffffffffu, s1, 2);
        if ((lane & 3) == 0) {
            int r0 = wm * 32 + i * 16 + lr;
            atomicAdd(&cwacc[r0], s0);
            atomicAdd(&cwacc[r0 + 8], s1);
        }
    }
    __syncthreads();
    if (tid < 128) {
        float cw = cwacc[tid];
        long gr = row0 + tid;
        int b = (int)(gr / EE), e = (int)(gr - (long)b * EE);
        int s = bonds[2 * e], d = bonds[2 * e + 1];
        const float* cd = g_cdn + gr * 3;
#pragma unroll
        for (int cc = 0; cc < 3; cc++) {
            float u = cd[cc] * cw;
            atomicAdd(&g_cupd[((long)b * NN + d) * 3 + cc], u);
            atomicAdd(&g_cupd[((long)b * NN + s) * 3 + cc], -u);
        }
    }
}

// ---------------- fused node kernel ----------------------------------------
__global__ void __launch_bounds__(256, 2)
node_fused_k(const __half* __restrict__ Wn1h, const float* __restrict__ bn1,
             const __half* __restrict__ Wn2h, const float* __restrict__ bn2)
{
    extern __shared__ char dyn[];
    __half* Th  = (__half*)dyn;
    __half* BRb = (__half*)(dyn + OFF_BR);

    __shared__ float b1s[128], b2s[128];

    const int tid = threadIdx.x;
    const int wid = tid >> 5, lane = tid & 31;
    const int wm = wid & 3, wn = wid >> 2;
    const int lr = lane >> 2, lc2 = (lane & 3) * 2;
    const long row0 = (long)blockIdx.x * 128;

    if (tid < 128) { b1s[tid] = bn1[tid]; b2s[tid] = bn2[tid]; }
    __syncthreads();

    const int arow = tid >> 1;
    const int aoff = (tid & 1) * 16;
    const long gra = row0 + arow;

    auto AB = [&](int i) { return Th + i * 128 * LDAh; };
    auto BR = [&](int i) { return BRb + i * BRCHUNK; };
    auto issue_A = [&](int ch, __half* Asb) {
        int k0 = ch << 5;
        const __half* src = ((k0 < 128) ? (g_htf + gra * HH) : (g_agg + gra * HH))
                            + (k0 & 127) + aoff;
        uint32_t dst = s2u(Asb + arow * LDAh + aoff);
        cp16(dst, src);
        cp16(dst + 16, src + 8);
    };

    float c[2][8][4];

    // ---- stage 1: n1 = silu([h|agg] @ Wn1 + b), K=256 ----
    zero_c(c);
    issue_A(0, AB(0)); issue_Bh(Wn1h, 0, BR(0), tid); CP_COMMIT();
    issue_A(1, AB(1)); issue_Bh(Wn1h, 32, BR(1), tid); CP_COMMIT();
    for (int ch = 0; ch < 8; ch++) {
        if (ch == 7) cp_wait<0>(); else cp_wait<1>();
        __syncthreads();
        if (ch + 2 < 8) {
            issue_A(ch + 2, AB((ch + 2) % 3));
            issue_Bh(Wn1h, (ch + 2) * 32, BR((ch + 2) % 3), tid);
            CP_COMMIT();
        }
        mma_chunk32(c, AB(ch % 3), LDAh, BR(ch % 3), wm, wn, lane);
    }
    __syncthreads();
    // prefetch stage-2 B chunks 0,1 behind the epilogue
    issue_Bh(Wn2h, 0, BR(0), tid); CP_COMMIT();
    issue_Bh(Wn2h, 32, BR(1), tid); CP_COMMIT();
#pragma unroll
    for (int i = 0; i < 2; i++) {
        int r0 = wm * 32 + i * 16 + lr;
#pragma unroll
        for (int j = 0; j < 8; j++) {
            int col = wn * 64 + j * 8 + lc2;
            float* cc = c[i][j];
            *(__half2*)&Th[r0 * LDTh + col] =
                __floats2half2_rn(silu_f(cc[0] + b1s[col]), silu_f(cc[1] + b1s[col + 1]));
            *(__half2*)&Th[(r0 + 8) * LDTh + col] =
                __floats2half2_rn(silu_f(cc[2] + b1s[col]), silu_f(cc[3] + b1s[col + 1]));
        }
    }
    __syncthreads();

    // ---- stage 2: h += n1 @ Wn2 + b (refresh g_htf) ----
    zero_c(c);
    for (int ch = 0; ch < 4; ch++) {
        if (ch == 3) cp_wait<0>(); else cp_wait<1>();
        __syncthreads();
        if (ch + 2 < 4) { issue_Bh(Wn2h, (ch + 2) * 32, BR((ch + 2) % 3), tid); CP_COMMIT(); }
        mma_chunk32(c, Th + ch * 32, LDTh, BR(ch % 3), wm, wn, lane);
    }
#pragma unroll
    for (int i = 0; i < 2; i++) {
        int r0 = wm * 32 + i * 16 + lr;
#pragma unroll
        for (int j = 0; j < 8; j++) {
            int col = wn * 64 + j * 8 + lc2;
            float* cc = c[i][j];
            long base0 = (row0 + r0) * HH + col;
            long base1 = (row0 + r0 + 8) * HH + col;
            float2 h0 = *(float2*)&g_h[base0];
            float2 h1 = *(float2*)&g_h[base1];
            float o0 = h0.x + cc[0] + b2s[col];
            float o1 = h0.y + cc[1] + b2s[col + 1];
            float o2 = h1.x + cc[2] + b2s[col];
            float o3 = h1.y + cc[3] + b2s[col + 1];
            *(float2*)&g_h[base0] = make_float2(o0, o1);
            *(float2*)&g_h[base1] = make_float2(o2, o3);
            *(__half2*)&g_htf[base0] = __floats2half2_rn(o0, o1);
            *(__half2*)&g_htf[base1] = __floats2half2_rn(o2, o3);
        }
    }
}

// ---------------- fused output kernel --------------------------------------
__global__ void __launch_bounds__(256, 2)
out_fused_k(const __half* __restrict__ Wo1h, const float* __restrict__ bo1,
            const float* __restrict__ Wo2, const float* __restrict__ bo2,
            const float* __restrict__ x_in, float* __restrict__ out)
{
    extern __shared__ char dyn[];
    __half* Th = (__half*)dyn;
    __half* B0 = (__half*)(dyn + OFF_BR);

    __shared__ float b1s[128];
    __shared__ float wo2s[128 * 3];
    __shared__ float oacc[128 * 3];

    const int tid = threadIdx.x;
    const int wid = tid >> 5, lane = tid & 31;
    const int wm = wid & 3, wn = wid >> 2;
    const int lr = lane >> 2, lc2 = (lane & 3) * 2;
    const long row0 = (long)blockIdx.x * 128;

    if (tid < 128) b1s[tid] = bo1[tid];
    for (int i = tid; i < 384; i += 256) { wo2s[i] = Wo2[i]; oacc[i] = 0.f; }

    {
        int row = tid >> 1;
        int off = (tid & 1) * 64;
        const __half* src = g_htf + (row0 + row) * HH + off;
        uint32_t dst = s2u(Th + row * LDTh + off);
#pragma unroll
        for (int q = 0; q < 8; q++) cp16(dst + q * 16, src + q * 8);
    }
    issue_Bfull(Wo1h, B0, tid);
    CP_COMMIT();
    cp_wait<0>();
    __syncthreads();

    float c[2][8][4];
    zero_c(c);
#pragma unroll
    for (int ch = 0; ch < 4; ch++)
        mma_chunk32(c, Th + ch * 32, LDTh, B0 + ch * 32 * LDBh, wm, wn, lane);
#pragma unroll
    for (int i = 0; i < 2; i++) {
        float s0[3] = {0.f, 0.f, 0.f};
        float s1[3] = {0.f, 0.f, 0.f};
#pragma unroll
        for (int j = 0; j < 8; j++) {
            int col = wn * 64 + j * 8 + lc2;
            float* cc = c[i][j];
            float v0 = silu_f(cc[0] + b1s[col]);
            float v1 = silu_f(cc[1] + b1s[col + 1]);
            float v2 = silu_f(cc[2] + b1s[col]);
            float v3 = silu_f(cc[3] + b1s[col + 1]);
#pragma unroll
            for (int k = 0; k < 3; k++) {
                s0[k] += v0 * wo2s[col * 3 + k] + v1 * wo2s[(col + 1) * 3 + k];
                s1[k] += v2 * wo2s[col * 3 + k] + v3 * wo2s[(col + 1) * 3 + k];
            }
        }
#pragma unroll
        for (int k = 0; k < 3; k++) {
            s0[k] += __shfl_xor_sync(0xffffffffu, s0[k], 1);
            s0[k] += __shfl_xor_sync(0xffffffffu, s0[k], 2);
            s1[k] += __shfl_xor_sync(0xffffffffu, s1[k], 1);
            s1[k] += __shfl_xor_sync(0xffffffffu, s1[k], 2);
        }
        if ((lane & 3) == 0) {
            int r0 = wm * 32 + i * 16 + lr;
#pragma unroll
            for (int k = 0; k < 3; k++) {
                atomicAdd(&oacc[r0 * 3 + k], s0[k]);
                atomicAdd(&oacc[(r0 + 8) * 3 + k], s1[k]);
            }
        }
    }
    __syncthreads();
    if (tid < 128) {
        long base = (row0 + tid) * 3;
#pragma unroll
        for (int cc = 0; cc < 3; cc++)
            out[base + cc] = oacc[tid * 3 + cc] + bo2[cc] + g_x[base + cc] - x_in[base + cc];
    }
}

// ---------------- setup kernels --------------------------------------------
__global__ void setupA_k(const float* __restrict__ t,
                         const float* __restrict__ W1, const float* __restrict__ b1,
                         const float* __restrict__ W2, const float* __restrict__ b2,
                         const float* __restrict__ emb,
                         const float* __restrict__ Wn, const float* __restrict__ bn,
                         const float* __restrict__ Wm1, const float* __restrict__ Wm2,
                         const float* __restrict__ Wc1, const float* __restrict__ Wn1,
                         const float* __restrict__ Wn2, const float* __restrict__ Wo1)
{
    const int tid = threadIdx.x;
    if (blockIdx.x == 0) {
        __shared__ float te[BB][TT];
        __shared__ float s1[BB][HH];
        const int half = TT / 2;
        for (int idx = tid; idx < BB * TT; idx += 256) {
            int b = idx / TT, k = idx % TT;
            int kk = (k < half) ? k : (k - half);
            float f = __expf((float)kk * (-logf(10000.f) / (float)(half - 1)));
            float a = t[b] * f;
            te[b][k] = (k < half) ? sinf(a) : cosf(a);
        }
        __syncthreads();
        if (tid < 128) {
            for (int b = 0; b < BB; b++) {
                float acc = b1[tid];
                for (int k = 0; k < TT; k++) acc += te[b][k] * W1[k * HH + tid];
                s1[b][tid] = silu_f(acc);
            }
        }
        __syncthreads();
        if (tid < 128) {
            for (int b = 0; b < BB; b++) {
                float acc = b2[tid];
                for (int k = 0; k < HH; k++) acc += s1[b][k] * W2[k * HH + tid];
                g_temb[b * HH + tid] = acc;
            }
        }
    } else if (blockIdx.x == 1) {
        for (int idx = tid; idx < 4 * HH; idx += 256) {
            int a = idx >> 7, j = idx & 127;
            float acc = bn[j];
            for (int k = 0; k < HH; k++) acc += emb[a * HH + k] * Wn[k * HH + j];
            g_table4[idx] = acc;
        }
    } else {
        long rid = (long)(blockIdx.x - 2) * 256 + tid;
        long rstride = (long)(gridDim.x - 2) * 256;
        for (long i = rid; i < 4L * 257 * 128; i += rstride) g_wm1[i] = __float2half_rn(Wm1[i]);
        for (long i = rid; i < 4L * 128 * 128; i += rstride) g_wm2[i] = __float2half_rn(Wm2[i]);
        for (long i = rid; i < 4L * 128 * 128; i += rstride) g_wc1[i] = __float2half_rn(Wc1[i]);
        for (long i = rid; i < 4L * 256 * 128; i += rstride) g_wn1[i] = __float2half_rn(Wn1[i]);
        for (long i = rid; i < 4L * 128 * 128; i += rstride) g_wn2[i] = __float2half_rn(Wn2[i]);
        for (long i = rid; i < 128L * 128; i += rstride)     g_wo1[i] = __float2half_rn(Wo1[i]);
    }
}

__global__ void setupB_k(const int* __restrict__ types, const float* __restrict__ x,
                         const int* __restrict__ bonds)
{
    const long N1 = (long)BB * NN * HH;
    const long N2 = N1 + BB * NN * 3;
    const long N3 = N2 + BB * NN * 3;
    const long N4 = N3 + BB * EE;
    const long stride = (long)gridDim.x * 256;
    for (long idx = (long)blockIdx.x * 256 + threadIdx.x; idx < N4; idx += stride) {
        if (idx < N1) {
            int j = (int)(idx & 127);
            long bn = idx >> 7;
            int n = (int)(bn % NN), b = (int)(bn / NN);
            float v = g_table4[types[n] * HH + j] + g_temb[b * HH + j];
            g_h[idx] = v;
            g_htf[idx] = __float2half_rn(v);
        } else if (idx < N2) {
            long i = idx - N1;
            g_x[i] = x[i];
        } else if (idx < N3) {
            g_cupd[idx - N2] = 0.f;
        } else {
            long i = idx - N3;
            int b = (int)(i / EE), e = (int)(i - (long)b * EE);
            int s = bonds[2 * e], d = bonds[2 * e + 1];
            const float* xs = x + ((long)b * NN + s) * 3;
            const float* xd = x + ((long)b * NN + d) * 3;
            float dx = xd[0] - xs[0], dy = xd[1] - xs[1], dz = xd[2] - xs[2];
            float dist = sqrtf(dx * dx + dy * dy + dz * dz);
            g_dist[i] = dist;
            float inv = 1.f / (dist + 1e-8f);
            g_cdn[i * 3 + 0] = dx * inv;
            g_cdn[i * 3 + 1] = dy * inv;
            g_cdn[i * 3 + 2] = dz * inv;
        }
    }
}

// per-layer (l>=1): edge geometry from g_x
__global__ void prep_k(const int* __restrict__ bonds)
{
    int i = blockIdx.x * 256 + threadIdx.x;
    if (i >= BB * EE) return;
    int b = i / EE, e = i - b * EE;
    int s = bonds[2 * e], d = bonds[2 * e + 1];
    const float* xs = g_x + ((long)b * NN + s) * 3;
    const float* xd = g_x + ((long)b * NN + d) * 3;
    float dx = xd[0] - xs[0], dy = xd[1] - xs[1], dz = xd[2] - xs[2];
    float dist = sqrtf(dx * dx + dy * dy + dz * dz);
    g_dist[i] = dist;
    float inv = 1.f / (dist + 1e-8f);
    g_cdn[i * 3 + 0] = dx * inv;
    g_cdn[i * 3 + 1] = dy * inv;
    g_cdn[i * 3 + 2] = dz * inv;
}

// ---------------- CSR + gather kernels --------------------------------------
__global__ void zero_i_k(int* __restrict__ p, int n)
{
    int idx = blockIdx.x * 256 + threadIdx.x;
    if (idx < n) p[idx] = 0;
}
__global__ void deg_count_k(const int* __restrict__ bonds)
{
    int e = blockIdx.x * 256 + threadIdx.x;
    if (e >= EE) return;
    atomicAdd(&g_deg[bonds[2 * e]], 1);
    atomicAdd(&g_deg[bonds[2 * e + 1]], 1);
}
__global__ void scan_k()
{
    __shared__ int sh[256];
    __shared__ int base;
    int tid = threadIdx.x;
    if (tid == 0) base = 0;
    __syncthreads();
    for (int i0 = 0; i0 < NN; i0 += 256) {
        int i = i0 + tid;
        int v = (i < NN) ? g_deg[i] : 0;
        sh[tid] = v;
        __syncthreads();
        for (int o = 1; o < 256; o <<= 1) {
            int t = (tid >= o) ? sh[tid - o] : 0;
            __syncthreads();
            sh[tid] += t;
            __syncthreads();
        }
        int excl = base + sh[tid] - v;
        if (i < NN) { g_off[i] = excl; g_cur[i] = excl; }
        __syncthreads();
        if (tid == 255) base += sh[255];
        __syncthreads();
    }
    if (tid == 0) g_off[NN] = base;
}
__global__ void fill_k(const int* __restrict__ bonds)
{
    int e = blockIdx.x * 256 + threadIdx.x;
    if (e >= EE) return;
    int s = bonds[2 * e], d = bonds[2 * e + 1];
    int p = atomicAdd(&g_cur[s], 1); g_csr[p] = e;
    int q = atomicAdd(&g_cur[d], 1); g_csr[q] = e;
}

__global__ void agg_gather_k()
{
    int warp = (blockIdx.x * 256 + threadIdx.x) >> 5;
    int lane = threadIdx.x & 31;
    if (warp >= BB * NN) return;
    int b = warp / NN, n = warp - b * NN;
    int o0 = g_off[n], o1 = g_off[n + 1];
    float acc[4] = {0.f, 0.f, 0.f, 0.f};
    for (int j = o0; j < o1; j++) {
        int e = g_csr[j];
        const __half2* row = (const __half2*)(g_m + ((long)b * EE + e) * HH) + lane * 2;
        float2 v0 = __half22float2(row[0]);
        float2 v1 = __half22float2(row[1]);
        acc[0] += v0.x; acc[1] += v0.y; acc[2] += v1.x; acc[3] += v1.y;
    }
    __half2* dst = (__half2*)(g_agg + (long)warp * HH) + lane * 2;
    dst[0] = __floats2half2_rn(acc[0], acc[1]);
    dst[1] = __floats2half2_rn(acc[2], acc[3]);
}

__global__ void x_update_k()
{
    int idx = blockIdx.x * 256 + threadIdx.x;
    if (idx >= BB * NN * 3) return;
    int n = (idx / 3) % NN;
    g_x[idx] += g_cupd[idx] / fmaxf((float)g_deg[n], 1.f);
    g_cupd[idx] = 0.f;
}

// ---------------- launch ---------------------------------------------------
static inline int cdiv(long n, int b) { return (int)((n + b - 1) / b); }

extern "C" void kernel_launch(void* const* d_in, const int* in_sizes, int n_in,
                              void* d_out, int out_size)
{
    const float* x      = (const float*)d_in[0];
    const float* t      = (const float*)d_in[1];
    const int*   types  = (const int*)d_in[2];
    const int*   bonds  = (const int*)d_in[3];
    const float* emb    = (const float*)d_in[4];
    const float* W_t1   = (const float*)d_in[5];
    const float* b_t1   = (const float*)d_in[6];
    const float* W_t2   = (const float*)d_in[7];
    const float* b_t2   = (const float*)d_in[8];
    const float* W_node = (const float*)d_in[9];
    const float* b_node = (const float*)d_in[10];
    const float* Wm1    = (const float*)d_in[11];
    const float* bm1    = (const float*)d_in[12];
    const float* Wm2    = (const float*)d_in[13];
    const float* bm2    = (const float*)d_in[14];
    const float* Wn1    = (const float*)d_in[15];
    const float* bn1    = (const float*)d_in[16];
    const float* Wn2    = (const float*)d_in[17];
    const float* bn2    = (const float*)d_in[18];
    const float* Wc1    = (const float*)d_in[19];
    const float* bc1    = (const float*)d_in[20];
    const float* Wc2    = (const float*)d_in[21];
    const float* Wo1    = (const float*)d_in[22];
    const float* bo1    = (const float*)d_in[23];
    const float* Wo2    = (const float*)d_in[24];
    const float* bo2    = (const float*)d_in[25];
    float* out = (float*)d_out;

    __half *p_wm1, *p_wm2, *p_wc1, *p_wn1, *p_wn2, *p_wo1;
    int *p_deg;
    cudaGetSymbolAddress((void**)&p_wm1, g_wm1);
    cudaGetSymbolAddress((void**)&p_wm2, g_wm2);
    cudaGetSymbolAddress((void**)&p_wc1, g_wc1);
    cudaGetSymbolAddress((void**)&p_wn1, g_wn1);
    cudaGetSymbolAddress((void**)&p_wn2, g_wn2);
    cudaGetSymbolAddress((void**)&p_wo1, g_wo1);
    cudaGetSymbolAddress((void**)&p_deg, g_deg);

    cudaFuncSetAttribute(edge_fused_k, cudaFuncAttributeMaxDynamicSharedMemorySize, FUSE_SMEM);
    cudaFuncSetAttribute(node_fused_k, cudaFuncAttributeMaxDynamicSharedMemorySize, FUSE_SMEM);
    cudaFuncSetAttribute(out_fused_k, cudaFuncAttributeMaxDynamicSharedMemorySize, OUT_SMEM);

    const int gridE = BB * EE / 128;  // 2500
    const int gridN = BB * NN / 128;  // 1250

    setupA_k<<<194, 256>>>(t, W_t1, b_t1, W_t2, b_t2, emb, W_node, b_node,
                           Wm1, Wm2, Wc1, Wn1, Wn2, Wo1);
    setupB_k<<<4096, 256>>>(types, x, bonds);
    zero_i_k<<<cdiv(NN, 256), 256>>>(p_deg, NN);

    for (int l = 0; l < LL; l++) {
        if (l > 0) prep_k<<<cdiv((long)BB * EE, 256), 256>>>(bonds);

        edge_fused_k<<<gridE, 256, FUSE_SMEM>>>(
            p_wm1 + (long)l * 257 * 128, bm1 + l * 128,
            Wm1 + ((long)l * 257 + 256) * 128,
            p_wm2 + (long)l * 16384, bm2 + l * 128,
            p_wc1 + (long)l * 16384, bc1 + l * 128, Wc2 + l * 128, bonds);

        if (l == 0) {
            deg_count_k<<<cdiv(EE, 256), 256>>>(bonds);
            scan_k<<<1, 256>>>();
            fill_k<<<cdiv(EE, 256), 256>>>(bonds);
        }

        agg_gather_k<<<cdiv((long)BB * NN * 32, 256), 256>>>();

        node_fused_k<<<gridN, 256, FUSE_SMEM>>>(
            p_wn1 + (long)l * 256 * 128, bn1 + l * 128,
            p_wn2 + (long)l * 16384, bn2 + l * 128);

        x_update_k<<<cdiv((long)BB * NN * 3, 256), 256>>>();
    }

    out_fused_k<<<gridN, 256, OUT_SMEM>>>(p_wo1, bo1, Wo2, bo2, x, out);
}